// round 1
// baseline (speedup 1.0000x reference)
#include <cuda_runtime.h>

// ---------------------------------------------------------------------------
// NeuroVPR Vanilla SNN: 3-layer LIF network, T=3 timesteps.
//   h1[all t] = dvs @ W1^T + b1          (one big GEMM, 69.3 GF, state-free)
//   per t: LIF1 -> s1@W2^T+b2 -> LIF2 -> s2@W3^T+b3 -> LIF3 -> out=s3(t=2)
// GEMM: fp32 with packed fma.rn.f32x2 (K-pair split), 128x128x16 tiles,
// 8x8 per-thread micro-tile, conflict-free fragment layout.
// ---------------------------------------------------------------------------

#define B_ 16384
#define T_ 3
#define D_ 2752
#define H_ 256
#define O_ 100

#define BM 128
#define BN 128
#define BK 16

// Scratch state (static device globals; no runtime allocation)
__device__ float g_h1[(size_t)B_ * T_ * H_];   // [b*3+t][h]
__device__ float g_v1[(size_t)B_ * H_];
__device__ float g_s1[(size_t)B_ * H_];
__device__ float g_v2[(size_t)B_ * H_];
__device__ float g_s2[(size_t)B_ * H_];
__device__ float g_v3[(size_t)B_ * O_];

__device__ __forceinline__ void ffma2(unsigned long long& c,
                                      unsigned long long a,
                                      unsigned long long b) {
    asm("fma.rn.f32x2 %0, %1, %2, %0;" : "+l"(c) : "l"(a), "l"(b));
}

// LIF update, rounding matched to reference: v += (x - v) * 0.5; spike at v>=1
__device__ __forceinline__ void lif_c(float hval, float vin, float& vout, float& sout) {
    float vn = __fadd_rn(vin, __fmul_rn(__fsub_rn(hval, vin), 0.5f));
    bool sp = (vn >= 1.0f);
    vout = sp ? 0.0f : vn;
    sout = sp ? 1.0f : 0.0f;
}

__device__ __forceinline__ void compute_tile(const float2 (*As2)[BM],
                                             const float2 (*Bs2)[BN],
                                             int tx, int ty,
                                             unsigned long long acc[8][8]) {
#pragma unroll
    for (int kp = 0; kp < BK / 2; ++kp) {
        unsigned long long a[8], b[8];
        const ulonglong2* Ak = reinterpret_cast<const ulonglong2*>(&As2[kp][0]);
        const ulonglong2* Bk = reinterpret_cast<const ulonglong2*>(&Bs2[kp][0]);
        ulonglong2 a01 = Ak[ty * 2];
        ulonglong2 a23 = Ak[ty * 2 + 1];
        ulonglong2 a45 = Ak[32 + ty * 2];
        ulonglong2 a67 = Ak[32 + ty * 2 + 1];
        a[0] = a01.x; a[1] = a01.y; a[2] = a23.x; a[3] = a23.y;
        a[4] = a45.x; a[5] = a45.y; a[6] = a67.x; a[7] = a67.y;
#pragma unroll
        for (int c = 0; c < 4; ++c) {
            ulonglong2 bb = Bk[c * 16 + tx];
            b[2 * c] = bb.x;
            b[2 * c + 1] = bb.y;
        }
#pragma unroll
        for (int i = 0; i < 8; ++i)
#pragma unroll
            for (int j = 0; j < 8; ++j)
                ffma2(acc[i][j], a[i], b[j]);
    }
}

// EPI = 0: store h = acc + bias into Sout (row-major [M][N])
// EPI = 1: LIF epilogue: read/write V (zeros at t==0), store spikes into Sout
template <int EPI>
__global__ void __launch_bounds__(256) snn_gemm_kernel(
    const float* __restrict__ A, const float* __restrict__ W,
    const float* __restrict__ bias, float* __restrict__ Sout,
    float* __restrict__ V, int t, int M, int N, int K) {
    __shared__ __align__(16) float2 As2[BK / 2][BM];
    __shared__ __align__(16) float2 Bs2[BK / 2][BN];

    const int tid = threadIdx.x;
    const int tx = tid & 15;
    const int ty = tid >> 4;
    const int m0 = blockIdx.x * BM;
    const int n0 = blockIdx.y * BN;

    unsigned long long acc[8][8];
#pragma unroll
    for (int i = 0; i < 8; ++i)
#pragma unroll
        for (int j = 0; j < 8; ++j) acc[i][j] = 0ULL;

    float4 ra[2], rb[2];

    // prologue: load tile 0
#pragma unroll
    for (int u = 0; u < 2; ++u) {
        int f = tid + u * 256;
        int row = f >> 2, kvec = f & 3;
        ra[u] = *(const float4*)(A + (size_t)(m0 + row) * K + kvec * 4);
        int n = n0 + row;
        rb[u] = (n < N) ? *(const float4*)(W + (size_t)n * K + kvec * 4)
                        : make_float4(0.f, 0.f, 0.f, 0.f);
    }
#pragma unroll
    for (int u = 0; u < 2; ++u) {
        int f = tid + u * 256;
        int row = f >> 2, kvec = f & 3;
        As2[kvec * 2][row]     = make_float2(ra[u].x, ra[u].y);
        As2[kvec * 2 + 1][row] = make_float2(ra[u].z, ra[u].w);
        Bs2[kvec * 2][row]     = make_float2(rb[u].x, rb[u].y);
        Bs2[kvec * 2 + 1][row] = make_float2(rb[u].z, rb[u].w);
    }
    __syncthreads();

    for (int kt = BK; kt < K; kt += BK) {
        // prefetch next tile into registers (overlaps with compute below)
#pragma unroll
        for (int u = 0; u < 2; ++u) {
            int f = tid + u * 256;
            int row = f >> 2, kvec = f & 3;
            ra[u] = *(const float4*)(A + (size_t)(m0 + row) * K + kt + kvec * 4);
            int n = n0 + row;
            rb[u] = (n < N) ? *(const float4*)(W + (size_t)n * K + kt + kvec * 4)
                            : make_float4(0.f, 0.f, 0.f, 0.f);
        }
        compute_tile(As2, Bs2, tx, ty, acc);
        __syncthreads();
#pragma unroll
        for (int u = 0; u < 2; ++u) {
            int f = tid + u * 256;
            int row = f >> 2, kvec = f & 3;
            As2[kvec * 2][row]     = make_float2(ra[u].x, ra[u].y);
            As2[kvec * 2 + 1][row] = make_float2(ra[u].z, ra[u].w);
            Bs2[kvec * 2][row]     = make_float2(rb[u].x, rb[u].y);
            Bs2[kvec * 2 + 1][row] = make_float2(rb[u].z, rb[u].w);
        }
        __syncthreads();
    }
    compute_tile(As2, Bs2, tx, ty, acc);

    // epilogue
#pragma unroll
    for (int i = 0; i < 8; ++i) {
        int m = m0 + ((i < 4) ? (ty * 4 + i) : (64 + ty * 4 + (i - 4)));
#pragma unroll
        for (int j = 0; j < 8; ++j) {
            int n = n0 + (j >> 1) * 32 + tx * 2 + (j & 1);
            if (n < N) {
                union { unsigned long long u; float2 f; } cv;
                cv.u = acc[i][j];
                float h = __fadd_rn(__fadd_rn(cv.f.x, cv.f.y), bias[n]);
                size_t idx = (size_t)m * N + n;
                if (EPI == 0) {
                    Sout[idx] = h;
                } else {
                    float v = (t == 0) ? 0.0f : V[idx];
                    float vo, so;
                    lif_c(h, v, vo, so);
                    V[idx] = vo;
                    Sout[idx] = so;
                }
            }
        }
    }
}

// LIF for layer 1: reads precomputed h1[(b*3+t)*H + h], updates v1, writes s1
__global__ void lif1_kernel(const float* __restrict__ h1, float* __restrict__ v1,
                            float* __restrict__ s1, int t) {
    int i = blockIdx.x * blockDim.x + threadIdx.x;  // float4 index over [B_*H_/4]
    int e = i * 4;
    int b = e >> 8;       // / H_ (H_ == 256)
    int h = e & 255;      // % H_
    float4 hv = *(const float4*)(h1 + (size_t)(b * 3 + t) * H_ + h);
    float4 v = (t == 0) ? make_float4(0.f, 0.f, 0.f, 0.f)
                        : *(const float4*)(v1 + e);
    float4 vo, so;
    lif_c(hv.x, v.x, vo.x, so.x);
    lif_c(hv.y, v.y, vo.y, so.y);
    lif_c(hv.z, v.z, vo.z, so.z);
    lif_c(hv.w, v.w, vo.w, so.w);
    *(float4*)(v1 + e) = vo;
    *(float4*)(s1 + e) = so;
}

extern "C" void kernel_launch(void* const* d_in, const int* in_sizes, int n_in,
                              void* d_out, int out_size) {
    const float* dvs = (const float*)d_in[0];
    const float* W1  = (const float*)d_in[1];
    const float* b1  = (const float*)d_in[2];
    const float* W2  = (const float*)d_in[3];
    const float* b2  = (const float*)d_in[4];
    const float* W3  = (const float*)d_in[5];
    const float* b3  = (const float*)d_in[6];
    float* out = (float*)d_out;

    float *h1, *v1, *s1, *v2, *s2, *v3;
    cudaGetSymbolAddress((void**)&h1, g_h1);
    cudaGetSymbolAddress((void**)&v1, g_v1);
    cudaGetSymbolAddress((void**)&s1, g_s1);
    cudaGetSymbolAddress((void**)&v2, g_v2);
    cudaGetSymbolAddress((void**)&s2, g_s2);
    cudaGetSymbolAddress((void**)&v3, g_v3);

    // Layer 1 for all timesteps at once: [B*T, D] @ [D, H] -> h1[b*3+t][h]
    snn_gemm_kernel<0><<<dim3((B_ * T_) / BM, H_ / BN), 256>>>(
        dvs, W1, b1, h1, nullptr, 0, B_ * T_, H_, D_);

    for (int t = 0; t < T_; ++t) {
        lif1_kernel<<<(B_ * H_ / 4) / 256, 256>>>(h1, v1, s1, t);
        // layer 2: s1 @ W2^T + b2, LIF fused into epilogue
        snn_gemm_kernel<1><<<dim3(B_ / BM, H_ / BN), 256>>>(
            s1, W2, b2, s2, v2, t, B_, H_, H_);
        // layer 3: s2 @ W3^T + b3, LIF fused; writes spikes straight to d_out
        // (t=2 write lands last -> final output)
        snn_gemm_kernel<1><<<dim3(B_ / BM, 1), 256>>>(
            s2, W3, b3, out, v3, t, B_, O_, H_);
    }
}

// round 3
// speedup vs baseline: 1.4524x; 1.4524x over previous
#include <cuda_runtime.h>
#include <cuda_bf16.h>
#include <cstdint>

// ---------------------------------------------------------------------------
// NeuroVPR SNN via mma.sync (compute_103-portable tensor path; tcgen05 is
// rejected by the harness's non-'a' virtual arch).
//  L1: exact 3-way bf16 split of A and W, 6 products (error ~ fp32 noise).
//  L2/L3: binary-spike A (exact bf16) x 3-way split W = exact products.
// ---------------------------------------------------------------------------

#define B_ 16384
#define T_ 3
#define D_ 2752
#define H_ 256
#define O_ 100

// ---- scratch ----
__device__ float g_h1[(size_t)B_ * T_ * H_];
__device__ float g_v1[(size_t)B_ * H_];
__device__ float g_v2[(size_t)B_ * H_];
__device__ float g_v3[(size_t)B_ * 128];
__device__ __nv_bfloat16 g_s1b[(size_t)B_ * H_];
__device__ __nv_bfloat16 g_s2b[(size_t)B_ * H_];
__device__ __nv_bfloat16 g_W1s[3 * H_ * D_];
__device__ __nv_bfloat16 g_W2s[3 * H_ * H_];
__device__ __nv_bfloat16 g_W3s[3 * 128 * H_];   // padded to 128 rows

// ======================= helpers =======================
__device__ __forceinline__ uint32_t smem_u32(const void* p) {
    uint32_t a;
    asm("{ .reg .u64 t; cvta.to.shared.u64 t, %1; cvt.u32.u64 %0, t; }"
        : "=r"(a) : "l"(p));
    return a;
}
#define CP_ASYNC16(dst, src) \
    asm volatile("cp.async.cg.shared.global [%0], [%1], 16;" :: "r"(dst), "l"(src))
#define CP_COMMIT() asm volatile("cp.async.commit_group;" ::: "memory")
#define CP_WAIT0() asm volatile("cp.async.wait_group 0;" ::: "memory")
#define LDSM4(r0, r1, r2, r3, addr) \
    asm volatile("ldmatrix.sync.aligned.m8n8.x4.shared.b16 {%0,%1,%2,%3}, [%4];" \
        : "=r"(r0), "=r"(r1), "=r"(r2), "=r"(r3) : "r"(addr))
#define MMA16816(d, a, b) \
    asm volatile("mma.sync.aligned.m16n8k16.row.col.f32.bf16.bf16.f32 " \
        "{%0,%1,%2,%3}, {%4,%5,%6,%7}, {%8,%9}, {%0,%1,%2,%3};" \
        : "+f"((d)[0]), "+f"((d)[1]), "+f"((d)[2]), "+f"((d)[3]) \
        : "r"((a)[0]), "r"((a)[1]), "r"((a)[2]), "r"((a)[3]), "r"((b)[0]), "r"((b)[1]))

__device__ __forceinline__ void split3(float x, __nv_bfloat16& a0,
                                       __nv_bfloat16& a1, __nv_bfloat16& a2) {
    a0 = __float2bfloat16_rn(x);
    float r1 = x - __bfloat162float(a0);   // exact
    a1 = __float2bfloat16_rn(r1);
    float r2 = r1 - __bfloat162float(a1);  // exact
    a2 = __float2bfloat16_rn(r2);
}
__device__ __forceinline__ uint32_t pack_bf2(__nv_bfloat16 lo, __nv_bfloat16 hi) {
    return (uint32_t)__bfloat16_as_ushort(lo) | ((uint32_t)__bfloat16_as_ushort(hi) << 16);
}
__device__ __forceinline__ void lif_c(float hval, float vin, float& vout, float& sout) {
    float vn = __fadd_rn(vin, __fmul_rn(__fsub_rn(hval, vin), 0.5f));
    bool sp = (vn >= 1.0f);
    vout = sp ? 0.0f : vn;
    sout = sp ? 1.0f : 0.0f;
}
// swizzled byte offset inside an 128x32-bf16 plane (row 64B = 4 x 16B chunks)
__device__ __forceinline__ uint32_t swz(int r, int c) {
    return (uint32_t)(r * 64 + ((c ^ ((r >> 1) & 3)) << 4));
}

// ======================= weight split kernels =======================
__global__ void split_w_kernel(const float* __restrict__ W, __nv_bfloat16* dst,
                               int n) {
    int i = blockIdx.x * 256 + threadIdx.x;
    float w = W[i];
    __nv_bfloat16 b0, b1, b2;
    split3(w, b0, b1, b2);
    dst[i] = b0; dst[i + n] = b1; dst[i + 2 * n] = b2;
}
__global__ void split_w3_kernel(const float* __restrict__ W3) {
    int i = blockIdx.x * 256 + threadIdx.x;      // over 128*H_
    int r = i >> 8, c = i & 255;
    float w = (r < O_) ? W3[r * H_ + c] : 0.0f;
    __nv_bfloat16 b0, b1, b2;
    split3(w, b0, b1, b2);
    g_W3s[i] = b0; g_W3s[i + 128 * H_] = b1; g_W3s[i + 2 * 128 * H_] = b2;
}

// ======================= unified mma.sync GEMM =======================
// MODE 1: L1  A=fp32 (split in-kernel, 3 planes), 6 products, epi: h -> Hout
// MODE 2: L2  A=bf16 spikes (1 plane),            3 products, epi: LIF -> bf16
// MODE 3: L3  A=bf16 spikes, N=100 predicated,    3 products, epi: LIF -> fp32
template <int MODE>
__global__ void __launch_bounds__(256) mma_gemm(
    const float* __restrict__ Af32, const __nv_bfloat16* __restrict__ Abf,
    const __nv_bfloat16* __restrict__ Ws, const float* __restrict__ bias,
    float* __restrict__ Hout, __nv_bfloat16* __restrict__ Sb,
    float* __restrict__ Sf, float* __restrict__ V, int t) {
    constexpr int Kdim = (MODE == 1) ? D_ : H_;
    constexpr int NST = Kdim / 32;
    constexpr size_t PL = (MODE == 1) ? (size_t)H_ * D_
                          : (MODE == 2) ? (size_t)H_ * H_ : (size_t)128 * H_;
    constexpr int NAPL = (MODE == 1) ? 3 : 1;          // A planes in smem
    constexpr int ABYTES = NAPL * 8192;
    constexpr int STAGE = ABYTES + 3 * 8192;
    constexpr int NP = (MODE == 1) ? 6 : 3;
    constexpr int PA[6] = {0, 0, 0, 1, 1, 2};
    constexpr int PB[6] = {0, 1, 2, 0, 1, 0};

    extern __shared__ char smem[];
    const uint32_t sb = smem_u32(smem);
    const int tid = threadIdx.x;
    const int lane = tid & 31;
    const int wid = tid >> 5;
    const int m0 = blockIdx.x * 128;
    const int n0 = blockIdx.y * 128;
    const int mbase = (wid >> 2) * 64;
    const int nbase = (wid & 3) * 32;

    float acc[4][4][4];
#pragma unroll
    for (int i = 0; i < 4; ++i)
#pragma unroll
        for (int j = 0; j < 4; ++j)
#pragma unroll
            for (int k = 0; k < 4; ++k) acc[i][j][k] = 0.0f;

    float4 ra[2][2];   // MODE1 A prefetch

    // ---- stage loaders ----
    auto load_B = [&](int ks, int buf) {
        int kc = ks * 32;
        uint32_t bb = sb + buf * STAGE + ABYTES;
#pragma unroll
        for (int u = 0; u < 6; ++u) {
            int f = tid + u * 256;
            int s = f >> 9, rem = f & 511, r = rem >> 2, c = rem & 3;
            const __nv_bfloat16* src = Ws + (size_t)s * PL + (size_t)(n0 + r) * Kdim + kc + c * 8;
            CP_ASYNC16(bb + s * 8192 + swz(r, c), src);
        }
    };
    auto load_A_direct = [&](int ks, int buf) {
        int kc = ks * 32;
        uint32_t ab = sb + buf * STAGE;
#pragma unroll
        for (int u = 0; u < 2; ++u) {
            int f = tid + u * 256;
            int r = f >> 2, c = f & 3;
            const __nv_bfloat16* src = Abf + (size_t)(m0 + r) * Kdim + kc + c * 8;
            CP_ASYNC16(ab + swz(r, c), src);
        }
    };
    auto ldg_A = [&](int ks) {
        int kc = ks * 32;
#pragma unroll
        for (int u = 0; u < 2; ++u) {
            int f2 = tid + u * 256;
            int r = f2 >> 2, c = f2 & 3;
            const float* g = Af32 + (size_t)(m0 + r) * Kdim + kc + c * 8;
            ra[u][0] = *(const float4*)g;
            ra[u][1] = *(const float4*)(g + 4);
        }
    };
    auto sts_A_split = [&](int buf) {
        uint32_t ab = sb + buf * STAGE;
#pragma unroll
        for (int u = 0; u < 2; ++u) {
            int f2 = tid + u * 256;
            int r = f2 >> 2, c = f2 & 3;
            float x[8] = {ra[u][0].x, ra[u][0].y, ra[u][0].z, ra[u][0].w,
                          ra[u][1].x, ra[u][1].y, ra[u][1].z, ra[u][1].w};
            __nv_bfloat16 s0[8], s1[8], s2[8];
#pragma unroll
            for (int j = 0; j < 8; ++j) split3(x[j], s0[j], s1[j], s2[j]);
            uint32_t off = swz(r, c);
            uint4 v0 = make_uint4(pack_bf2(s0[0], s0[1]), pack_bf2(s0[2], s0[3]),
                                  pack_bf2(s0[4], s0[5]), pack_bf2(s0[6], s0[7]));
            uint4 v1 = make_uint4(pack_bf2(s1[0], s1[1]), pack_bf2(s1[2], s1[3]),
                                  pack_bf2(s1[4], s1[5]), pack_bf2(s1[6], s1[7]));
            uint4 v2 = make_uint4(pack_bf2(s2[0], s2[1]), pack_bf2(s2[2], s2[3]),
                                  pack_bf2(s2[4], s2[5]), pack_bf2(s2[6], s2[7]));
            asm volatile("st.shared.v4.b32 [%0], {%1,%2,%3,%4};" :: "r"(ab + off),
                         "r"(v0.x), "r"(v0.y), "r"(v0.z), "r"(v0.w));
            asm volatile("st.shared.v4.b32 [%0], {%1,%2,%3,%4};" :: "r"(ab + 8192 + off),
                         "r"(v1.x), "r"(v1.y), "r"(v1.z), "r"(v1.w));
            asm volatile("st.shared.v4.b32 [%0], {%1,%2,%3,%4};" :: "r"(ab + 16384 + off),
                         "r"(v2.x), "r"(v2.y), "r"(v2.z), "r"(v2.w));
        }
    };

    // ---- per-lane ldmatrix geometry ----
    const int a_row = mbase + (lane & 7) + ((lane >> 3) & 1) * 8;  // + ma*16
    const int a_chb = (lane >> 4);                                  // + kk*2
    const int b_row = nbase + (lane & 7) + (lane >> 4) * 8;         // + n16*16
    const int b_chb = ((lane >> 3) & 1);                            // + kk*2

    auto compute = [&](int buf) {
        uint32_t ab = sb + buf * STAGE;
        uint32_t bb = ab + ABYTES;
#pragma unroll
        for (int kk = 0; kk < 2; ++kk) {
            uint32_t afr[NAPL][4][4];
            uint32_t bfr[3][8];
#pragma unroll
            for (int s = 0; s < NAPL; ++s)
#pragma unroll
                for (int ma = 0; ma < 4; ++ma) {
                    int r = a_row + ma * 16;
                    int c = kk * 2 + a_chb;
                    uint32_t ad = ab + s * 8192 + swz(r, c);
                    LDSM4(afr[s][ma][0], afr[s][ma][1], afr[s][ma][2], afr[s][ma][3], ad);
                }
#pragma unroll
            for (int s = 0; s < 3; ++s)
#pragma unroll
                for (int h = 0; h < 2; ++h) {
                    int r = b_row + h * 16;
                    int c = kk * 2 + b_chb;
                    uint32_t bd = bb + s * 8192 + swz(r, c);
                    LDSM4(bfr[s][h * 4 + 0], bfr[s][h * 4 + 1],
                          bfr[s][h * 4 + 2], bfr[s][h * 4 + 3], bd);
                }
#pragma unroll
            for (int p = 0; p < NP; ++p) {
                const int sa = (MODE == 1) ? PA[p] : 0;
                const int sbp = PB[p];
#pragma unroll
                for (int ma = 0; ma < 4; ++ma)
#pragma unroll
                    for (int na = 0; na < 4; ++na)
                        MMA16816(acc[ma][na], afr[sa][ma], &bfr[sbp][na * 2]);
            }
        }
    };

    // ---- prologue: stage 0 ----
    load_B(0, 0);
    if (MODE == 1) { ldg_A(0); sts_A_split(0); } else { load_A_direct(0, 0); }
    CP_COMMIT();
    CP_WAIT0();
    __syncthreads();

    // ---- main loop ----
    for (int ks = 0; ks < NST; ++ks) {
        int cur = ks & 1;
        bool more = (ks + 1 < NST);
        if (more) {
            load_B(ks + 1, cur ^ 1);
            if (MODE == 1) ldg_A(ks + 1); else load_A_direct(ks + 1, cur ^ 1);
            CP_COMMIT();
        }
        compute(cur);
        __syncthreads();
        if (more) {
            if (MODE == 1) sts_A_split(cur ^ 1);
            CP_WAIT0();
            __syncthreads();
        }
    }

    // ---- epilogue ----
#pragma unroll
    for (int ma = 0; ma < 4; ++ma) {
        int row0 = m0 + mbase + ma * 16 + (lane >> 2);
#pragma unroll
        for (int na = 0; na < 4; ++na) {
            int col0 = n0 + nbase + na * 8 + (lane & 3) * 2;
            const float* a4 = acc[ma][na];
#pragma unroll
            for (int h = 0; h < 2; ++h) {
                int row = row0 + h * 8;
                float cx = a4[h * 2 + 0], cy = a4[h * 2 + 1];
                if (MODE == 1) {
                    float2 o = make_float2(cx + bias[col0], cy + bias[col0 + 1]);
                    *(float2*)(Hout + (size_t)row * H_ + col0) = o;
                } else if (MODE == 2) {
                    size_t idx = (size_t)row * H_ + col0;
                    float2 v = (t == 0) ? make_float2(0.f, 0.f) : *(float2*)(V + idx);
                    float hx = __fadd_rn(cx, bias[col0]);
                    float hy = __fadd_rn(cy, bias[col0 + 1]);
                    float vox, voy, sox, soy;
                    lif_c(hx, v.x, vox, sox);
                    lif_c(hy, v.y, voy, soy);
                    *(float2*)(V + idx) = make_float2(vox, voy);
                    *(uint32_t*)(Sb + idx) =
                        pack_bf2(__float2bfloat16_rn(sox), __float2bfloat16_rn(soy));
                } else {
                    if (col0 < O_) {
                        size_t vidx = (size_t)row * 128 + col0;
                        float2 v = (t == 0) ? make_float2(0.f, 0.f) : *(float2*)(V + vidx);
                        float hx = __fadd_rn(cx, bias[col0]);
                        float hy = __fadd_rn(cy, bias[col0 + 1]);
                        float vox, voy, sox, soy;
                        lif_c(hx, v.x, vox, sox);
                        lif_c(hy, v.y, voy, soy);
                        *(float2*)(V + vidx) = make_float2(vox, voy);
                        *(float2*)(Sf + (size_t)row * O_ + col0) = make_float2(sox, soy);
                    }
                }
            }
        }
    }
}

// ======================= LIF layer 1 =======================
__global__ void lif1_kernel(const float* __restrict__ h1, float* __restrict__ v1,
                            __nv_bfloat16* __restrict__ s1, int t) {
    int i = blockIdx.x * blockDim.x + threadIdx.x;
    int e = i * 4;
    int b = e >> 8;
    int h = e & 255;
    float4 hv = *(const float4*)(h1 + (size_t)(b * 3 + t) * H_ + h);
    float4 v = (t == 0) ? make_float4(0.f, 0.f, 0.f, 0.f) : *(const float4*)(v1 + e);
    float4 vo, so;
    lif_c(hv.x, v.x, vo.x, so.x);
    lif_c(hv.y, v.y, vo.y, so.y);
    lif_c(hv.z, v.z, vo.z, so.z);
    lif_c(hv.w, v.w, vo.w, so.w);
    *(float4*)(v1 + e) = vo;
    uint2 sp;
    sp.x = pack_bf2(__float2bfloat16_rn(so.x), __float2bfloat16_rn(so.y));
    sp.y = pack_bf2(__float2bfloat16_rn(so.z), __float2bfloat16_rn(so.w));
    *(uint2*)(s1 + e) = sp;
}

extern "C" void kernel_launch(void* const* d_in, const int* in_sizes, int n_in,
                              void* d_out, int out_size) {
    const float* dvs = (const float*)d_in[0];
    const float* W1  = (const float*)d_in[1];
    const float* b1  = (const float*)d_in[2];
    const float* W2  = (const float*)d_in[3];
    const float* b2  = (const float*)d_in[4];
    const float* W3  = (const float*)d_in[5];
    const float* b3  = (const float*)d_in[6];
    float* out = (float*)d_out;

    float *h1, *v1, *v2, *v3;
    __nv_bfloat16 *s1b, *s2b, *w1s, *w2s;
    cudaGetSymbolAddress((void**)&h1, g_h1);
    cudaGetSymbolAddress((void**)&v1, g_v1);
    cudaGetSymbolAddress((void**)&v2, g_v2);
    cudaGetSymbolAddress((void**)&v3, g_v3);
    cudaGetSymbolAddress((void**)&s1b, g_s1b);
    cudaGetSymbolAddress((void**)&s2b, g_s2b);
    cudaGetSymbolAddress((void**)&w1s, g_W1s);
    cudaGetSymbolAddress((void**)&w2s, g_W2s);
    __nv_bfloat16* w3s;
    cudaGetSymbolAddress((void**)&w3s, g_W3s);

    const int SM1 = 2 * (3 + 3) * 8192;   // 98304
    const int SM2 = 2 * (1 + 3) * 8192;   // 65536
    cudaFuncSetAttribute(mma_gemm<1>, cudaFuncAttributeMaxDynamicSharedMemorySize, SM1);
    cudaFuncSetAttribute(mma_gemm<2>, cudaFuncAttributeMaxDynamicSharedMemorySize, SM2);
    cudaFuncSetAttribute(mma_gemm<3>, cudaFuncAttributeMaxDynamicSharedMemorySize, SM2);

    // weight splits (exact 3-way bf16)
    split_w_kernel<<<(H_ * D_) / 256, 256>>>(W1, w1s, H_ * D_);
    split_w_kernel<<<(H_ * H_) / 256, 256>>>(W2, w2s, H_ * H_);
    split_w3_kernel<<<(128 * H_) / 256, 256>>>(W3);

    // layer 1, all timesteps: [B*T, D] @ W1^T -> g_h1
    mma_gemm<1><<<dim3((B_ * T_) / 128, H_ / 128), 256, SM1>>>(
        dvs, nullptr, w1s, b1, h1, nullptr, nullptr, nullptr, 0);

    for (int t = 0; t < T_; ++t) {
        lif1_kernel<<<(B_ * H_ / 4) / 256, 256>>>(h1, v1, s1b, t);
        mma_gemm<2><<<dim3(B_ / 128, H_ / 128), 256, SM2>>>(
            nullptr, s1b, w2s, b2, nullptr, s2b, nullptr, v2, t);
        mma_gemm<3><<<dim3(B_ / 128, 1), 256, SM2>>>(
            nullptr, s2b, w3s, b3, nullptr, nullptr, out, v3, t);
    }
}

// round 5
// speedup vs baseline: 2.7589x; 1.8996x over previous
#include <cuda_runtime.h>
#include <cuda_fp16.h>
#include <cstdint>

// ---------------------------------------------------------------------------
// NeuroVPR SNN via mma.sync fp16 2-way exact-split (scale 2^6).
//  L1: A,W each split into 2 fp16 words; 3 products (drop l*l ~ 2^-22).
//  L2/L3: spikes exact in fp16; W split 2-way -> 2 products.
// Error class ~ fp32 accumulation noise (proven flip-free in R1/R3).
// ---------------------------------------------------------------------------

#define B_ 16384
#define T_ 3
#define D_ 2752
#define H_ 256
#define O_ 100

// ---- scratch ----
__device__ float g_h1[(size_t)B_ * T_ * H_];
__device__ float g_v1[(size_t)B_ * H_];
__device__ float g_v2[(size_t)B_ * H_];
__device__ float g_v3[(size_t)B_ * 128];
__device__ __half g_s1b[(size_t)B_ * H_];
__device__ __half g_s2b[(size_t)B_ * H_];
__device__ __half g_W1s[2 * H_ * D_];
__device__ __half g_W2s[2 * H_ * H_];
__device__ __half g_W3s[2 * 128 * H_];   // padded to 128 rows

#define WSCALE 64.0f
#define INV_S1 (1.0f / 4096.0f)   // L1: A and W both scaled 2^6
#define INV_S2 (1.0f / 64.0f)     // L2/3: only W scaled

// ======================= helpers =======================
__device__ __forceinline__ uint32_t smem_u32(const void* p) {
    uint32_t a;
    asm("{ .reg .u64 t; cvta.to.shared.u64 t, %1; cvt.u32.u64 %0, t; }"
        : "=r"(a) : "l"(p));
    return a;
}
#define CP_ASYNC16(dst, src) \
    asm volatile("cp.async.cg.shared.global [%0], [%1], 16;" :: "r"(dst), "l"(src))
#define CP_COMMIT() asm volatile("cp.async.commit_group;" ::: "memory")
#define CP_WAIT0() asm volatile("cp.async.wait_group 0;" ::: "memory")
#define LDSM4(r0, r1, r2, r3, addr) \
    asm volatile("ldmatrix.sync.aligned.m8n8.x4.shared.b16 {%0,%1,%2,%3}, [%4];" \
        : "=r"(r0), "=r"(r1), "=r"(r2), "=r"(r3) : "r"(addr))
#define MMA16816(d, a, b) \
    asm volatile("mma.sync.aligned.m16n8k16.row.col.f32.f16.f16.f32 " \
        "{%0,%1,%2,%3}, {%4,%5,%6,%7}, {%8,%9}, {%0,%1,%2,%3};" \
        : "+f"((d)[0]), "+f"((d)[1]), "+f"((d)[2]), "+f"((d)[3]) \
        : "r"((a)[0]), "r"((a)[1]), "r"((a)[2]), "r"((a)[3]), "r"((b)[0]), "r"((b)[1]))

__device__ __forceinline__ void split2(float x, __half& h, __half& l) {
    float xs = x * WSCALE;
    h = __float2half_rn(xs);
    l = __float2half_rn(xs - __half2float(h));
}
__device__ __forceinline__ uint32_t pack_h2(__half lo, __half hi) {
    return (uint32_t)__half_as_ushort(lo) | ((uint32_t)__half_as_ushort(hi) << 16);
}
__device__ __forceinline__ void lif_c(float hval, float vin, float& vout, float& sout) {
    float vn = __fadd_rn(vin, __fmul_rn(__fsub_rn(hval, vin), 0.5f));
    bool sp = (vn >= 1.0f);
    vout = sp ? 0.0f : vn;
    sout = sp ? 1.0f : 0.0f;
}
// swizzled byte offset inside a 128x32-f16 plane (row 64B = 4 x 16B chunks)
__device__ __forceinline__ uint32_t swz(int r, int c) {
    return (uint32_t)(r * 64 + ((c ^ ((r >> 1) & 3)) << 4));
}

// ======================= weight split kernels =======================
__global__ void split_w_kernel(const float* __restrict__ W, __half* dst, int n) {
    int i = blockIdx.x * 256 + threadIdx.x;
    __half h, l;
    split2(W[i], h, l);
    dst[i] = h; dst[i + n] = l;
}
__global__ void split_w3_kernel(const float* __restrict__ W3) {
    int i = blockIdx.x * 256 + threadIdx.x;      // over 128*H_
    int r = i >> 8, c = i & 255;
    float w = (r < O_) ? W3[r * H_ + c] : 0.0f;
    __half h, l;
    split2(w, h, l);
    g_W3s[i] = h; g_W3s[i + 128 * H_] = l;
}

// ======================= unified mma.sync GEMM =======================
// MODE 1: L1  A=fp32 (split in-kernel, 2 planes), 3 products, epi: h -> Hout
// MODE 2: L2  A=fp16 spikes (1 plane),            2 products, epi: LIF -> fp16
// MODE 3: L3  A=fp16 spikes, N=100 predicated,    2 products, epi: LIF -> fp32
template <int MODE>
__global__ void __launch_bounds__(256, 2) mma_gemm(
    const float* __restrict__ Af32, const __half* __restrict__ Ahf,
    const __half* __restrict__ Ws, const float* __restrict__ bias,
    float* __restrict__ Hout, __half* __restrict__ Sb,
    float* __restrict__ Sf, float* __restrict__ V, int t) {
    constexpr int Kdim = (MODE == 1) ? D_ : H_;
    constexpr int NST = Kdim / 32;
    constexpr size_t PL = (MODE == 1) ? (size_t)H_ * D_
                          : (MODE == 2) ? (size_t)H_ * H_ : (size_t)128 * H_;
    constexpr int NAPL = (MODE == 1) ? 2 : 1;          // A planes in smem
    constexpr int ABYTES = NAPL * 8192;
    constexpr int STAGE = ABYTES + 2 * 8192;

    extern __shared__ char smem[];
    const uint32_t sb = smem_u32(smem);
    const int tid = threadIdx.x;
    const int lane = tid & 31;
    const int wid = tid >> 5;
    const int m0 = blockIdx.x * 128;
    const int n0 = blockIdx.y * 128;
    const int mbase = (wid >> 2) * 64;
    const int nbase = (wid & 3) * 32;

    float acc[4][4][4];
#pragma unroll
    for (int i = 0; i < 4; ++i)
#pragma unroll
        for (int j = 0; j < 4; ++j)
#pragma unroll
            for (int k = 0; k < 4; ++k) acc[i][j][k] = 0.0f;

    float4 ra[2][2];   // MODE1 A prefetch

    // ---- stage loaders ----
    auto load_B = [&](int ks, int buf) {
        int kc = ks * 32;
        uint32_t bb = sb + buf * STAGE + ABYTES;
#pragma unroll
        for (int u = 0; u < 4; ++u) {
            int f = tid + u * 256;
            int s = f >> 9, rem = f & 511, r = rem >> 2, c = rem & 3;
            const __half* src = Ws + (size_t)s * PL + (size_t)(n0 + r) * Kdim + kc + c * 8;
            CP_ASYNC16(bb + s * 8192 + swz(r, c), src);
        }
    };
    auto load_A_direct = [&](int ks, int buf) {
        int kc = ks * 32;
        uint32_t ab = sb + buf * STAGE;
#pragma unroll
        for (int u = 0; u < 2; ++u) {
            int f = tid + u * 256;
            int r = f >> 2, c = f & 3;
            const __half* src = Ahf + (size_t)(m0 + r) * Kdim + kc + c * 8;
            CP_ASYNC16(ab + swz(r, c), src);
        }
    };
    auto ldg_A = [&](int ks) {
        int kc = ks * 32;
#pragma unroll
        for (int u = 0; u < 2; ++u) {
            int f2 = tid + u * 256;
            int r = f2 >> 2, c = f2 & 3;
            const float* g = Af32 + (size_t)(m0 + r) * Kdim + kc + c * 8;
            ra[u][0] = *(const float4*)g;
            ra[u][1] = *(const float4*)(g + 4);
        }
    };
    auto sts_A_split = [&](int buf) {
        uint32_t ab = sb + buf * STAGE;
#pragma unroll
        for (int u = 0; u < 2; ++u) {
            int f2 = tid + u * 256;
            int r = f2 >> 2, c = f2 & 3;
            float x[8] = {ra[u][0].x, ra[u][0].y, ra[u][0].z, ra[u][0].w,
                          ra[u][1].x, ra[u][1].y, ra[u][1].z, ra[u][1].w};
            __half s0[8], s1[8];
#pragma unroll
            for (int j = 0; j < 8; ++j) split2(x[j], s0[j], s1[j]);
            uint32_t off = swz(r, c);
            uint4 v0 = make_uint4(pack_h2(s0[0], s0[1]), pack_h2(s0[2], s0[3]),
                                  pack_h2(s0[4], s0[5]), pack_h2(s0[6], s0[7]));
            uint4 v1 = make_uint4(pack_h2(s1[0], s1[1]), pack_h2(s1[2], s1[3]),
                                  pack_h2(s1[4], s1[5]), pack_h2(s1[6], s1[7]));
            asm volatile("st.shared.v4.b32 [%0], {%1,%2,%3,%4};" :: "r"(ab + off),
                         "r"(v0.x), "r"(v0.y), "r"(v0.z), "r"(v0.w));
            asm volatile("st.shared.v4.b32 [%0], {%1,%2,%3,%4};" :: "r"(ab + 8192 + off),
                         "r"(v1.x), "r"(v1.y), "r"(v1.z), "r"(v1.w));
        }
    };

    // ---- per-lane ldmatrix geometry ----
    const int a_row = mbase + (lane & 7) + ((lane >> 3) & 1) * 8;  // + ma*16
    const int a_chb = (lane >> 4);                                  // + kk*2
    const int b_row = nbase + (lane & 7) + (lane >> 4) * 8;         // + n16*16
    const int b_chb = ((lane >> 3) & 1);                            // + kk*2

    auto compute = [&](int buf) {
        uint32_t ab = sb + buf * STAGE;
        uint32_t bb = ab + ABYTES;
#pragma unroll
        for (int kk = 0; kk < 2; ++kk) {
            uint32_t afr[NAPL][4][4];
#pragma unroll
            for (int s = 0; s < NAPL; ++s)
#pragma unroll
                for (int ma = 0; ma < 4; ++ma) {
                    int r = a_row + ma * 16;
                    int c = kk * 2 + a_chb;
                    uint32_t ad = ab + s * 8192 + swz(r, c);
                    LDSM4(afr[s][ma][0], afr[s][ma][1], afr[s][ma][2], afr[s][ma][3], ad);
                }
            // B planes one at a time (keeps fragment registers low)
#pragma unroll
            for (int pb = 0; pb < 2; ++pb) {
                uint32_t bfr[8];
#pragma unroll
                for (int h = 0; h < 2; ++h) {
                    int r = b_row + h * 16;
                    int c = kk * 2 + b_chb;
                    uint32_t bd = bb + pb * 8192 + swz(r, c);
                    LDSM4(bfr[h * 4 + 0], bfr[h * 4 + 1],
                          bfr[h * 4 + 2], bfr[h * 4 + 3], bd);
                }
                // products for this B plane:
                //  MODE1: pb==0 -> A0,A1 ; pb==1 -> A0   (3 total)
                //  MODE2/3: A0 only                      (2 total)
                const int nsa = (MODE == 1 && pb == 0) ? 2 : 1;
#pragma unroll
                for (int sa = 0; sa < nsa; ++sa)
#pragma unroll
                    for (int ma = 0; ma < 4; ++ma)
#pragma unroll
                        for (int na = 0; na < 4; ++na)
                            MMA16816(acc[ma][na], afr[sa][ma], &bfr[na * 2]);
            }
        }
    };

    // ---- prologue: stage 0 ----
    load_B(0, 0);
    if (MODE == 1) { ldg_A(0); sts_A_split(0); } else { load_A_direct(0, 0); }
    CP_COMMIT();
    CP_WAIT0();
    __syncthreads();

    // ---- main loop ----
    for (int ks = 0; ks < NST; ++ks) {
        int cur = ks & 1;
        bool more = (ks + 1 < NST);
        if (more) {
            load_B(ks + 1, cur ^ 1);
            if (MODE == 1) ldg_A(ks + 1); else load_A_direct(ks + 1, cur ^ 1);
            CP_COMMIT();
        }
        compute(cur);
        __syncthreads();
        if (more) {
            if (MODE == 1) sts_A_split(cur ^ 1);
            CP_WAIT0();
            __syncthreads();
        }
    }

    // ---- epilogue ----
    constexpr float IS = (MODE == 1) ? INV_S1 : INV_S2;
#pragma unroll
    for (int ma = 0; ma < 4; ++ma) {
        int row0 = m0 + mbase + ma * 16 + (lane >> 2);
#pragma unroll
        for (int na = 0; na < 4; ++na) {
            int col0 = n0 + nbase + na * 8 + (lane & 3) * 2;
            const float* a4 = acc[ma][na];
#pragma unroll
            for (int h = 0; h < 2; ++h) {
                int row = row0 + h * 8;
                float cx = __fmul_rn(a4[h * 2 + 0], IS);   // exact (power of 2)
                float cy = __fmul_rn(a4[h * 2 + 1], IS);
                if (MODE == 1) {
                    float2 o = make_float2(__fadd_rn(cx, bias[col0]),
                                           __fadd_rn(cy, bias[col0 + 1]));
                    *(float2*)(Hout + (size_t)row * H_ + col0) = o;
                } else if (MODE == 2) {
                    size_t idx = (size_t)row * H_ + col0;
                    float2 v = (t == 0) ? make_float2(0.f, 0.f) : *(float2*)(V + idx);
                    float hx = __fadd_rn(cx, bias[col0]);
                    float hy = __fadd_rn(cy, bias[col0 + 1]);
                    float vox, voy, sox, soy;
                    lif_c(hx, v.x, vox, sox);
                    lif_c(hy, v.y, voy, soy);
                    *(float2*)(V + idx) = make_float2(vox, voy);
                    *(uint32_t*)(Sb + idx) =
                        pack_h2(__float2half_rn(sox), __float2half_rn(soy));
                } else {
                    if (col0 < O_) {
                        size_t vidx = (size_t)row * 128 + col0;
                        float2 v = (t == 0) ? make_float2(0.f, 0.f) : *(float2*)(V + vidx);
                        float hx = __fadd_rn(cx, bias[col0]);
                        float hy = __fadd_rn(cy, bias[col0 + 1]);
                        float vox, voy, sox, soy;
                        lif_c(hx, v.x, vox, sox);
                        lif_c(hy, v.y, voy, soy);
                        *(float2*)(V + vidx) = make_float2(vox, voy);
                        *(float2*)(Sf + (size_t)row * O_ + col0) = make_float2(sox, soy);
                    }
                }
            }
        }
    }
}

// ======================= LIF layer 1 =======================
__global__ void lif1_kernel(const float* __restrict__ h1, float* __restrict__ v1,
                            __half* __restrict__ s1, int t) {
    int i = blockIdx.x * blockDim.x + threadIdx.x;
    int e = i * 4;
    int b = e >> 8;
    int h = e & 255;
    float4 hv = *(const float4*)(h1 + (size_t)(b * 3 + t) * H_ + h);
    float4 v = (t == 0) ? make_float4(0.f, 0.f, 0.f, 0.f) : *(const float4*)(v1 + e);
    float4 vo, so;
    lif_c(hv.x, v.x, vo.x, so.x);
    lif_c(hv.y, v.y, vo.y, so.y);
    lif_c(hv.z, v.z, vo.z, so.z);
    lif_c(hv.w, v.w, vo.w, so.w);
    *(float4*)(v1 + e) = vo;
    uint2 sp;
    sp.x = pack_h2(__float2half_rn(so.x), __float2half_rn(so.y));
    sp.y = pack_h2(__float2half_rn(so.z), __float2half_rn(so.w));
    *(uint2*)(s1 + e) = sp;
}

extern "C" void kernel_launch(void* const* d_in, const int* in_sizes, int n_in,
                              void* d_out, int out_size) {
    const float* dvs = (const float*)d_in[0];
    const float* W1  = (const float*)d_in[1];
    const float* b1  = (const float*)d_in[2];
    const float* W2  = (const float*)d_in[3];
    const float* b2  = (const float*)d_in[4];
    const float* W3  = (const float*)d_in[5];
    const float* b3  = (const float*)d_in[6];
    float* out = (float*)d_out;

    float *h1, *v1, *v2, *v3;
    __half *s1b, *s2b, *w1s, *w2s, *w3s;
    cudaGetSymbolAddress((void**)&h1, g_h1);
    cudaGetSymbolAddress((void**)&v1, g_v1);
    cudaGetSymbolAddress((void**)&v2, g_v2);
    cudaGetSymbolAddress((void**)&v3, g_v3);
    cudaGetSymbolAddress((void**)&s1b, g_s1b);
    cudaGetSymbolAddress((void**)&s2b, g_s2b);
    cudaGetSymbolAddress((void**)&w1s, g_W1s);
    cudaGetSymbolAddress((void**)&w2s, g_W2s);
    cudaGetSymbolAddress((void**)&w3s, g_W3s);

    const int SM1 = 2 * (2 + 2) * 8192;   // 65536
    const int SM2 = 2 * (1 + 2) * 8192;   // 49152
    cudaFuncSetAttribute(mma_gemm<1>, cudaFuncAttributeMaxDynamicSharedMemorySize, SM1);
    cudaFuncSetAttribute(mma_gemm<2>, cudaFuncAttributeMaxDynamicSharedMemorySize, SM2);
    cudaFuncSetAttribute(mma_gemm<3>, cudaFuncAttributeMaxDynamicSharedMemorySize, SM2);

    // weight splits (exact 2-way fp16, scale 2^6)
    split_w_kernel<<<(H_ * D_) / 256, 256>>>(W1, w1s, H_ * D_);
    split_w_kernel<<<(H_ * H_) / 256, 256>>>(W2, w2s, H_ * H_);
    split_w3_kernel<<<(128 * H_) / 256, 256>>>(W3);

    // layer 1, all timesteps: [B*T, D] @ W1^T -> g_h1
    mma_gemm<1><<<dim3((B_ * T_) / 128, H_ / 128), 256, SM1>>>(
        dvs, nullptr, w1s, b1, h1, nullptr, nullptr, nullptr, 0);

    for (int t = 0; t < T_; ++t) {
        lif1_kernel<<<(B_ * H_ / 4) / 256, 256>>>(h1, v1, s1b, t);
        mma_gemm<2><<<dim3(B_ / 128, H_ / 128), 256, SM2>>>(
            nullptr, s1b, w2s, b2, nullptr, s2b, nullptr, v2, t);
        mma_gemm<3><<<dim3(B_ / 128, 1), 256, SM2>>>(
            nullptr, s2b, w3s, b3, nullptr, nullptr, out, v3, t);
    }
}

// round 6
// speedup vs baseline: 2.8512x; 1.0335x over previous
#include <cuda_runtime.h>
#include <cuda_fp16.h>
#include <cstdint>

// ---------------------------------------------------------------------------
// NeuroVPR SNN via mma.sync fp16 2-way exact-split (scale 2^6).
//  L1: A,W each split into 2 fp16 words; 3 products (drop l*l ~ 2^-22).
//      64M x 256N tiles: A loaded+split exactly once (halves DRAM + split work).
//  L2/L3: spikes exact in fp16; W split 2-way -> 2 products.
// ---------------------------------------------------------------------------

#define B_ 16384
#define T_ 3
#define D_ 2752
#define H_ 256
#define O_ 100

// ---- scratch ----
__device__ float g_h1[(size_t)B_ * T_ * H_];
__device__ float g_v1[(size_t)B_ * H_];
__device__ float g_v2[(size_t)B_ * H_];
__device__ float g_v3[(size_t)B_ * 128];
__device__ __half g_s1b[(size_t)B_ * H_];
__device__ __half g_s2b[(size_t)B_ * H_];
__device__ __half g_W1s[2 * H_ * D_];
__device__ __half g_W2s[2 * H_ * H_];
__device__ __half g_W3s[2 * 128 * H_];   // padded to 128 rows

#define WSCALE 64.0f
#define INV_S1 (1.0f / 4096.0f)   // L1: A and W both scaled 2^6
#define INV_S2 (1.0f / 64.0f)     // L2/3: only W scaled

// ======================= helpers =======================
__device__ __forceinline__ uint32_t smem_u32(const void* p) {
    uint32_t a;
    asm("{ .reg .u64 t; cvta.to.shared.u64 t, %1; cvt.u32.u64 %0, t; }"
        : "=r"(a) : "l"(p));
    return a;
}
#define CP_ASYNC16(dst, src) \
    asm volatile("cp.async.cg.shared.global [%0], [%1], 16;" :: "r"(dst), "l"(src))
#define CP_COMMIT() asm volatile("cp.async.commit_group;" ::: "memory")
#define CP_WAIT0() asm volatile("cp.async.wait_group 0;" ::: "memory")
#define LDSM4(r0, r1, r2, r3, addr) \
    asm volatile("ldmatrix.sync.aligned.m8n8.x4.shared.b16 {%0,%1,%2,%3}, [%4];" \
        : "=r"(r0), "=r"(r1), "=r"(r2), "=r"(r3) : "r"(addr))
#define MMA16816(d, a, b) \
    asm volatile("mma.sync.aligned.m16n8k16.row.col.f32.f16.f16.f32 " \
        "{%0,%1,%2,%3}, {%4,%5,%6,%7}, {%8,%9}, {%0,%1,%2,%3};" \
        : "+f"((d)[0]), "+f"((d)[1]), "+f"((d)[2]), "+f"((d)[3]) \
        : "r"((a)[0]), "r"((a)[1]), "r"((a)[2]), "r"((a)[3]), "r"((b)[0]), "r"((b)[1]))

__device__ __forceinline__ void split2(float x, __half& h, __half& l) {
    float xs = x * WSCALE;
    h = __float2half_rn(xs);
    l = __float2half_rn(xs - __half2float(h));
}
__device__ __forceinline__ uint32_t pack_h2(__half lo, __half hi) {
    return (uint32_t)__half_as_ushort(lo) | ((uint32_t)__half_as_ushort(hi) << 16);
}
__device__ __forceinline__ void lif_c(float hval, float vin, float& vout, float& sout) {
    float vn = __fadd_rn(vin, __fmul_rn(__fsub_rn(hval, vin), 0.5f));
    bool sp = (vn >= 1.0f);
    vout = sp ? 0.0f : vn;
    sout = sp ? 1.0f : 0.0f;
}
// swizzled byte offset inside an Rx32-f16 plane (row 64B = 4 x 16B chunks)
__device__ __forceinline__ uint32_t swz(int r, int c) {
    return (uint32_t)(r * 64 + ((c ^ ((r >> 1) & 3)) << 4));
}

// ======================= weight split kernels =======================
__global__ void split_w_kernel(const float* __restrict__ W, __half* dst, int n) {
    int i = blockIdx.x * 256 + threadIdx.x;
    __half h, l;
    split2(W[i], h, l);
    dst[i] = h; dst[i + n] = l;
}
__global__ void split_w3_kernel(const float* __restrict__ W3) {
    int i = blockIdx.x * 256 + threadIdx.x;      // over 128*H_
    int r = i >> 8, c = i & 255;
    float w = (r < O_) ? W3[r * H_ + c] : 0.0f;
    __half h, l;
    split2(w, h, l);
    g_W3s[i] = h; g_W3s[i + 128 * H_] = l;
}

// ======================= unified mma.sync GEMM =======================
// MODE 1: L1  64Mx256N tile. A=fp32 split in-kernel (2 planes), 3 products.
// MODE 2: L2  128Mx128N. A=fp16 spikes, 2 products, epi: LIF -> fp16
// MODE 3: L3  128Mx128N(100). A=fp16 spikes, 2 products, epi: LIF -> fp32
template <int MODE>
__global__ void __launch_bounds__(256, 2) mma_gemm(
    const float* __restrict__ Af32, const __half* __restrict__ Ahf,
    const __half* __restrict__ Ws, const float* __restrict__ bias,
    float* __restrict__ Hout, __half* __restrict__ Sb,
    float* __restrict__ Sf, float* __restrict__ V, int t) {
    constexpr int Kdim = (MODE == 1) ? D_ : H_;
    constexpr int NST = Kdim / 32;
    constexpr size_t PL = (MODE == 1) ? (size_t)H_ * D_
                          : (MODE == 2) ? (size_t)H_ * H_ : (size_t)128 * H_;
    constexpr int BROWS = (MODE == 1) ? 256 : 128;     // B tile rows (N width)
    constexpr int APLANE = (MODE == 1) ? 4096 : 8192;  // bytes per A plane
    constexpr int BPLANE = BROWS * 64;                 // bytes per B plane
    constexpr int NAPL = (MODE == 1) ? 2 : 1;          // A planes in smem
    constexpr int ABYTES = NAPL * APLANE;
    constexpr int STAGE = ABYTES + 2 * BPLANE;
    constexpr int MA = (MODE == 1) ? 2 : 4;            // m16 tiles per warp
    constexpr int NA = (MODE == 1) ? 8 : 4;            // n8 tiles per warp

    extern __shared__ char smem[];
    const uint32_t sb = smem_u32(smem);
    const int tid = threadIdx.x;
    const int lane = tid & 31;
    const int wid = tid >> 5;
    const int m0 = blockIdx.x * ((MODE == 1) ? 64 : 128);
    const int n0 = blockIdx.y * 128;
    const int mbase = (MODE == 1) ? (wid & 1) * 32 : (wid >> 2) * 64;
    const int nbase = (MODE == 1) ? (wid >> 1) * 64 : (wid & 3) * 32;

    float acc[MA][NA][4];
#pragma unroll
    for (int i = 0; i < MA; ++i)
#pragma unroll
        for (int j = 0; j < NA; ++j)
#pragma unroll
            for (int k = 0; k < 4; ++k) acc[i][j][k] = 0.0f;

    float4 ra2[2];     // MODE1 A prefetch (8 fp32 = one 16B fp16 chunk/plane)
    float4 ra_m23[2][2];  // MODE2/3 unused

    // ---- stage loaders ----
    auto load_B = [&](int ks, int buf) {
        int kc = ks * 32;
        uint32_t bb = sb + buf * STAGE + ABYTES;
        constexpr int NU = (MODE == 1) ? 8 : 4;        // 2*BROWS*4 / 256
#pragma unroll
        for (int u = 0; u < NU; ++u) {
            int f = tid + u * 256;
            int s = f / (BROWS * 4), rem = f % (BROWS * 4), r = rem >> 2, c = rem & 3;
            const __half* src = Ws + (size_t)s * PL + (size_t)(n0 + r) * Kdim + kc + c * 8;
            CP_ASYNC16(bb + s * BPLANE + swz(r, c), src);
        }
    };
    auto load_A_direct = [&](int ks, int buf) {   // MODE 2/3
        int kc = ks * 32;
        uint32_t ab = sb + buf * STAGE;
#pragma unroll
        for (int u = 0; u < 2; ++u) {
            int f = tid + u * 256;
            int r = f >> 2, c = f & 3;
            const __half* src = Ahf + (size_t)(m0 + r) * Kdim + kc + c * 8;
            CP_ASYNC16(ab + swz(r, c), src);
        }
    };
    auto ldg_A = [&](int ks) {                    // MODE 1: 64 rows x 32 fp32
        int kc = ks * 32;
        int r = tid >> 2, c = tid & 3;
        const float* g = Af32 + (size_t)(m0 + r) * Kdim + kc + c * 8;
        ra2[0] = *(const float4*)g;
        ra2[1] = *(const float4*)(g + 4);
    };
    auto sts_A_split = [&](int buf) {
        uint32_t ab = sb + buf * STAGE;
        int r = tid >> 2, c = tid & 3;
        float x[8] = {ra2[0].x, ra2[0].y, ra2[0].z, ra2[0].w,
                      ra2[1].x, ra2[1].y, ra2[1].z, ra2[1].w};
        __half s0[8], s1[8];
#pragma unroll
        for (int j = 0; j < 8; ++j) split2(x[j], s0[j], s1[j]);
        uint32_t off = swz(r, c);
        uint4 v0 = make_uint4(pack_h2(s0[0], s0[1]), pack_h2(s0[2], s0[3]),
                              pack_h2(s0[4], s0[5]), pack_h2(s0[6], s0[7]));
        uint4 v1 = make_uint4(pack_h2(s1[0], s1[1]), pack_h2(s1[2], s1[3]),
                              pack_h2(s1[4], s1[5]), pack_h2(s1[6], s1[7]));
        asm volatile("st.shared.v4.b32 [%0], {%1,%2,%3,%4};" :: "r"(ab + off),
                     "r"(v0.x), "r"(v0.y), "r"(v0.z), "r"(v0.w));
        asm volatile("st.shared.v4.b32 [%0], {%1,%2,%3,%4};" :: "r"(ab + APLANE + off),
                     "r"(v1.x), "r"(v1.y), "r"(v1.z), "r"(v1.w));
    };
    auto ldg_A_m23 = [&](int ks) {};   // placeholder (unused)

    // ---- per-lane ldmatrix geometry ----
    const int a_row = mbase + (lane & 7) + ((lane >> 3) & 1) * 8;  // + ma*16
    const int a_chb = (lane >> 4);                                  // + kk*2
    const int b_row = nbase + (lane & 7) + (lane >> 4) * 8;         // + n16*16
    const int b_chb = ((lane >> 3) & 1);                            // + kk*2

    auto compute = [&](int buf) {
        uint32_t ab = sb + buf * STAGE;
        uint32_t bb = ab + ABYTES;
#pragma unroll
        for (int kk = 0; kk < 2; ++kk) {
            uint32_t afr[NAPL][MA][4];
#pragma unroll
            for (int s = 0; s < NAPL; ++s)
#pragma unroll
                for (int ma = 0; ma < MA; ++ma) {
                    int r = a_row + ma * 16;
                    int c = kk * 2 + a_chb;
                    uint32_t ad = ab + s * APLANE + swz(r, c);
                    LDSM4(afr[s][ma][0], afr[s][ma][1], afr[s][ma][2], afr[s][ma][3], ad);
                }
            // B planes one at a time (keeps fragment registers low)
#pragma unroll
            for (int pb = 0; pb < 2; ++pb) {
                uint32_t bfr[NA * 2];
#pragma unroll
                for (int h = 0; h < NA / 2; ++h) {
                    int r = b_row + h * 16;
                    int c = kk * 2 + b_chb;
                    uint32_t bd = bb + pb * BPLANE + swz(r, c);
                    LDSM4(bfr[h * 4 + 0], bfr[h * 4 + 1],
                          bfr[h * 4 + 2], bfr[h * 4 + 3], bd);
                }
                // products for this B plane:
                //  MODE1: pb==0 -> A0,A1 ; pb==1 -> A0   (3 total)
                //  MODE2/3: A0 only                      (2 total)
                const int nsa = (MODE == 1 && pb == 0) ? 2 : 1;
#pragma unroll
                for (int sa = 0; sa < nsa; ++sa)
#pragma unroll
                    for (int ma = 0; ma < MA; ++ma)
#pragma unroll
                        for (int na = 0; na < NA; ++na)
                            MMA16816(acc[ma][na], afr[sa][ma], &bfr[na * 2]);
            }
        }
    };

    // ---- prologue: stage 0 ----
    load_B(0, 0);
    if (MODE == 1) { ldg_A(0); sts_A_split(0); } else { load_A_direct(0, 0); }
    CP_COMMIT();
    CP_WAIT0();
    __syncthreads();

    // ---- main loop ----
    for (int ks = 0; ks < NST; ++ks) {
        int cur = ks & 1;
        bool more = (ks + 1 < NST);
        if (more) {
            load_B(ks + 1, cur ^ 1);
            if (MODE == 1) ldg_A(ks + 1); else load_A_direct(ks + 1, cur ^ 1);
            CP_COMMIT();
        }
        compute(cur);
        __syncthreads();
        if (more) {
            if (MODE == 1) sts_A_split(cur ^ 1);
            CP_WAIT0();
            __syncthreads();
        }
    }

    // ---- epilogue ----
    constexpr float IS = (MODE == 1) ? INV_S1 : INV_S2;
#pragma unroll
    for (int ma = 0; ma < MA; ++ma) {
        int row0 = m0 + mbase + ma * 16 + (lane >> 2);
#pragma unroll
        for (int na = 0; na < NA; ++na) {
            int col0 = n0 + nbase + na * 8 + (lane & 3) * 2;
            const float* a4 = acc[ma][na];
#pragma unroll
            for (int h = 0; h < 2; ++h) {
                int row = row0 + h * 8;
                float cx = __fmul_rn(a4[h * 2 + 0], IS);   // exact (power of 2)
                float cy = __fmul_rn(a4[h * 2 + 1], IS);
                if (MODE == 1) {
                    float2 o = make_float2(__fadd_rn(cx, bias[col0]),
                                           __fadd_rn(cy, bias[col0 + 1]));
                    *(float2*)(Hout + (size_t)row * H_ + col0) = o;
                } else if (MODE == 2) {
                    size_t idx = (size_t)row * H_ + col0;
                    float2 v = (t == 0) ? make_float2(0.f, 0.f) : *(float2*)(V + idx);
                    float hx = __fadd_rn(cx, bias[col0]);
                    float hy = __fadd_rn(cy, bias[col0 + 1]);
                    float vox, voy, sox, soy;
                    lif_c(hx, v.x, vox, sox);
                    lif_c(hy, v.y, voy, soy);
                    *(float2*)(V + idx) = make_float2(vox, voy);
                    *(uint32_t*)(Sb + idx) =
                        pack_h2(__float2half_rn(sox), __float2half_rn(soy));
                } else {
                    if (col0 < O_) {
                        size_t vidx = (size_t)row * 128 + col0;
                        float2 v = (t == 0) ? make_float2(0.f, 0.f) : *(float2*)(V + vidx);
                        float hx = __fadd_rn(cx, bias[col0]);
                        float hy = __fadd_rn(cy, bias[col0 + 1]);
                        float vox, voy, sox, soy;
                        lif_c(hx, v.x, vox, sox);
                        lif_c(hy, v.y, voy, soy);
                        *(float2*)(V + vidx) = make_float2(vox, voy);
                        *(float2*)(Sf + (size_t)row * O_ + col0) = make_float2(sox, soy);
                    }
                }
            }
        }
    }
}

// ======================= LIF layer 1 =======================
__global__ void lif1_kernel(const float* __restrict__ h1, float* __restrict__ v1,
                            __half* __restrict__ s1, int t) {
    int i = blockIdx.x * blockDim.x + threadIdx.x;
    int e = i * 4;
    int b = e >> 8;
    int h = e & 255;
    float4 hv = *(const float4*)(h1 + (size_t)(b * 3 + t) * H_ + h);
    float4 v = (t == 0) ? make_float4(0.f, 0.f, 0.f, 0.f) : *(const float4*)(v1 + e);
    float4 vo, so;
    lif_c(hv.x, v.x, vo.x, so.x);
    lif_c(hv.y, v.y, vo.y, so.y);
    lif_c(hv.z, v.z, vo.z, so.z);
    lif_c(hv.w, v.w, vo.w, so.w);
    *(float4*)(v1 + e) = vo;
    uint2 sp;
    sp.x = pack_h2(__float2half_rn(so.x), __float2half_rn(so.y));
    sp.y = pack_h2(__float2half_rn(so.z), __float2half_rn(so.w));
    *(uint2*)(s1 + e) = sp;
}

extern "C" void kernel_launch(void* const* d_in, const int* in_sizes, int n_in,
                              void* d_out, int out_size) {
    const float* dvs = (const float*)d_in[0];
    const float* W1  = (const float*)d_in[1];
    const float* b1  = (const float*)d_in[2];
    const float* W2  = (const float*)d_in[3];
    const float* b2  = (const float*)d_in[4];
    const float* W3  = (const float*)d_in[5];
    const float* b3  = (const float*)d_in[6];
    float* out = (float*)d_out;

    float *h1, *v1, *v2, *v3;
    __half *s1b, *s2b, *w1s, *w2s, *w3s;
    cudaGetSymbolAddress((void**)&h1, g_h1);
    cudaGetSymbolAddress((void**)&v1, g_v1);
    cudaGetSymbolAddress((void**)&v2, g_v2);
    cudaGetSymbolAddress((void**)&v3, g_v3);
    cudaGetSymbolAddress((void**)&s1b, g_s1b);
    cudaGetSymbolAddress((void**)&s2b, g_s2b);
    cudaGetSymbolAddress((void**)&w1s, g_W1s);
    cudaGetSymbolAddress((void**)&w2s, g_W2s);
    cudaGetSymbolAddress((void**)&w3s, g_W3s);

    const int SM1 = 2 * (2 * 4096 + 2 * 16384);   // 81920
    const int SM2 = 2 * (1 * 8192 + 2 * 8192);    // 49152
    cudaFuncSetAttribute(mma_gemm<1>, cudaFuncAttributeMaxDynamicSharedMemorySize, SM1);
    cudaFuncSetAttribute(mma_gemm<2>, cudaFuncAttributeMaxDynamicSharedMemorySize, SM2);
    cudaFuncSetAttribute(mma_gemm<3>, cudaFuncAttributeMaxDynamicSharedMemorySize, SM2);

    // weight splits (exact 2-way fp16, scale 2^6)
    split_w_kernel<<<(H_ * D_) / 256, 256>>>(W1, w1s, H_ * D_);
    split_w_kernel<<<(H_ * H_) / 256, 256>>>(W2, w2s, H_ * H_);
    split_w3_kernel<<<(128 * H_) / 256, 256>>>(W3);

    // layer 1, all timesteps: [B*T, D] @ W1^T -> g_h1  (64M x 256N tiles)
    mma_gemm<1><<<dim3((B_ * T_) / 64, 1), 256, SM1>>>(
        dvs, nullptr, w1s, b1, h1, nullptr, nullptr, nullptr, 0);

    for (int t = 0; t < T_; ++t) {
        lif1_kernel<<<(B_ * H_ / 4) / 256, 256>>>(h1, v1, s1b, t);
        mma_gemm<2><<<dim3(B_ / 128, H_ / 128), 256, SM2>>>(
            nullptr, s1b, w2s, b2, nullptr, s2b, nullptr, v2, t);
        mma_gemm<3><<<dim3(B_ / 128, 1), 256, SM2>>>(
            nullptr, s2b, w3s, b3, nullptr, nullptr, out, v3, t);
    }
}

// round 8
// speedup vs baseline: 2.9389x; 1.0308x over previous
#include <cuda_runtime.h>
#include <cuda_fp16.h>
#include <cstdint>

// ---------------------------------------------------------------------------
// NeuroVPR SNN via mma.sync fp16 2-way exact-split (scale 2^6).
//  L1: 128Mx256N CTA tiles, 512 thr, 3-stage single-sync pipeline.
//      A,W split into 2 fp16 words; 3 products (drop l*l ~ 2^-22).
//  L2/L3: spikes exact in fp16; W split 2-way -> 2 products; 3-stage pipe.
// ---------------------------------------------------------------------------

#define B_ 16384
#define T_ 3
#define D_ 2752
#define H_ 256
#define O_ 100

// ---- scratch ----
__device__ float g_h1[(size_t)B_ * T_ * H_];
__device__ float g_v1[(size_t)B_ * H_];
__device__ float g_v2[(size_t)B_ * H_];
__device__ float g_v3[(size_t)B_ * 128];
__device__ __half g_s1b[(size_t)B_ * H_];
__device__ __half g_s2b[(size_t)B_ * H_];
__device__ __half g_W1s[2 * H_ * D_];
__device__ __half g_W2s[2 * H_ * H_];
__device__ __half g_W3s[2 * 128 * H_];   // padded to 128 rows

#define WSCALE 64.0f
#define INV_S1 (1.0f / 4096.0f)   // L1: A and W both scaled 2^6
#define INV_S2 (1.0f / 64.0f)     // L2/3: only W scaled

// ======================= helpers =======================
__device__ __forceinline__ uint32_t smem_u32(const void* p) {
    uint32_t a;
    asm("{ .reg .u64 t; cvta.to.shared.u64 t, %1; cvt.u32.u64 %0, t; }"
        : "=r"(a) : "l"(p));
    return a;
}
#define CP_ASYNC16(dst, src) \
    asm volatile("cp.async.cg.shared.global [%0], [%1], 16;" :: "r"(dst), "l"(src))
#define CP_COMMIT() asm volatile("cp.async.commit_group;" ::: "memory")
#define CP_WAIT0() asm volatile("cp.async.wait_group 0;" ::: "memory")
#define CP_WAIT1() asm volatile("cp.async.wait_group 1;" ::: "memory")
#define LDSM4(r0, r1, r2, r3, addr) \
    asm volatile("ldmatrix.sync.aligned.m8n8.x4.shared.b16 {%0,%1,%2,%3}, [%4];" \
        : "=r"(r0), "=r"(r1), "=r"(r2), "=r"(r3) : "r"(addr))
#define MMA16816(d, a, b) \
    asm volatile("mma.sync.aligned.m16n8k16.row.col.f32.f16.f16.f32 " \
        "{%0,%1,%2,%3}, {%4,%5,%6,%7}, {%8,%9}, {%0,%1,%2,%3};" \
        : "+f"((d)[0]), "+f"((d)[1]), "+f"((d)[2]), "+f"((d)[3]) \
        : "r"((a)[0]), "r"((a)[1]), "r"((a)[2]), "r"((a)[3]), "r"((b)[0]), "r"((b)[1]))

__device__ __forceinline__ void split2(float x, __half& h, __half& l) {
    float xs = x * WSCALE;
    h = __float2half_rn(xs);
    l = __float2half_rn(xs - __half2float(h));
}
__device__ __forceinline__ uint32_t pack_h2(__half lo, __half hi) {
    return (uint32_t)__half_as_ushort(lo) | ((uint32_t)__half_as_ushort(hi) << 16);
}
__device__ __forceinline__ void lif_c(float hval, float vin, float& vout, float& sout) {
    float vn = __fadd_rn(vin, __fmul_rn(__fsub_rn(hval, vin), 0.5f));
    bool sp = (vn >= 1.0f);
    vout = sp ? 0.0f : vn;
    sout = sp ? 1.0f : 0.0f;
}
// swizzled byte offset inside an Rx32-f16 plane (row 64B = 4 x 16B chunks)
__device__ __forceinline__ uint32_t swz(int r, int c) {
    return (uint32_t)(r * 64 + ((c ^ ((r >> 1) & 3)) << 4));
}

// ======================= weight split kernels =======================
__global__ void split_w_kernel(const float* __restrict__ W, __half* dst, int n) {
    int i = blockIdx.x * 256 + threadIdx.x;
    __half h, l;
    split2(W[i], h, l);
    dst[i] = h; dst[i + n] = l;
}
__global__ void split_w3_kernel(const float* __restrict__ W3) {
    int i = blockIdx.x * 256 + threadIdx.x;      // over 128*H_
    int r = i >> 8, c = i & 255;
    float w = (r < O_) ? W3[r * H_ + c] : 0.0f;
    __half h, l;
    split2(w, h, l);
    g_W3s[i] = h; g_W3s[i + 128 * H_] = l;
}

// ======================= Layer-1 GEMM: 128Mx256N, 512 thr, 3-stage ==========
#define NST1 (D_ / 32)            // 86
#define APL1 8192                 // 128 rows x 64 B
#define AB1  (2 * APL1)           // 16384
#define BPL1 16384                // 256 rows x 64 B
#define STG1 (AB1 + 2 * BPL1)     // 49152
#define SMEM1 (3 * STG1)          // 147456

__global__ void __launch_bounds__(512, 1) mma_gemm1(
    const float* __restrict__ Af32, const __half* __restrict__ Ws,
    const float* __restrict__ bias, float* __restrict__ Hout) {
    extern __shared__ char smem[];
    const uint32_t sb = smem_u32(smem);
    const int tid = threadIdx.x;
    const int lane = tid & 31;
    const int wid = tid >> 5;
    const int m0 = blockIdx.x * 128;
    const int mbase = (wid & 3) * 32;
    const int nbase = (wid >> 2) * 64;

    float acc[2][8][4];
#pragma unroll
    for (int i = 0; i < 2; ++i)
#pragma unroll
        for (int j = 0; j < 8; ++j)
#pragma unroll
            for (int k = 0; k < 4; ++k) acc[i][j][k] = 0.0f;

    float4 ra2[2];
    const int lr = tid >> 2, lc = tid & 3;

    auto ldg_A = [&](int ks) {
        const float* g = Af32 + (size_t)(m0 + lr) * D_ + ks * 32 + lc * 8;
        ra2[0] = *(const float4*)g;
        ra2[1] = *(const float4*)(g + 4);
    };
    auto sts_A_split = [&](int buf) {
        uint32_t ab = sb + buf * STG1;
        float x[8] = {ra2[0].x, ra2[0].y, ra2[0].z, ra2[0].w,
                      ra2[1].x, ra2[1].y, ra2[1].z, ra2[1].w};
        __half s0[8], s1[8];
#pragma unroll
        for (int j = 0; j < 8; ++j) split2(x[j], s0[j], s1[j]);
        uint32_t off = swz(lr, lc);
        uint4 v0 = make_uint4(pack_h2(s0[0], s0[1]), pack_h2(s0[2], s0[3]),
                              pack_h2(s0[4], s0[5]), pack_h2(s0[6], s0[7]));
        uint4 v1 = make_uint4(pack_h2(s1[0], s1[1]), pack_h2(s1[2], s1[3]),
                              pack_h2(s1[4], s1[5]), pack_h2(s1[6], s1[7]));
        asm volatile("st.shared.v4.b32 [%0], {%1,%2,%3,%4};" :: "r"(ab + off),
                     "r"(v0.x), "r"(v0.y), "r"(v0.z), "r"(v0.w));
        asm volatile("st.shared.v4.b32 [%0], {%1,%2,%3,%4};" :: "r"(ab + APL1 + off),
                     "r"(v1.x), "r"(v1.y), "r"(v1.z), "r"(v1.w));
    };
    auto load_B = [&](int ks, int buf) {
        int kc = ks * 32;
        uint32_t bb = sb + buf * STG1 + AB1;
#pragma unroll
        for (int u = 0; u < 4; ++u) {
            int f = tid + u * 512;
            int s = f >> 10, rem = f & 1023, r = rem >> 2, c = rem & 3;
            const __half* src = Ws + (size_t)s * (H_ * D_) + (size_t)r * D_ + kc + c * 8;
            CP_ASYNC16(bb + s * BPL1 + swz(r, c), src);
        }
    };

    const int a_row = mbase + (lane & 7) + ((lane >> 3) & 1) * 8;
    const int a_chb = (lane >> 4);
    const int b_row = nbase + (lane & 7) + (lane >> 4) * 8;
    const int b_chb = ((lane >> 3) & 1);

    auto compute = [&](int buf) {
        uint32_t ab = sb + buf * STG1;
        uint32_t bb = ab + AB1;
#pragma unroll
        for (int kk = 0; kk < 2; ++kk) {
            uint32_t afr[2][2][4];
#pragma unroll
            for (int s = 0; s < 2; ++s)
#pragma unroll
                for (int ma = 0; ma < 2; ++ma) {
                    uint32_t ad = ab + s * APL1 + swz(a_row + ma * 16, kk * 2 + a_chb);
                    LDSM4(afr[s][ma][0], afr[s][ma][1], afr[s][ma][2], afr[s][ma][3], ad);
                }
#pragma unroll
            for (int pb = 0; pb < 2; ++pb) {
                uint32_t bfr[16];
#pragma unroll
                for (int h = 0; h < 4; ++h) {
                    uint32_t bd = bb + pb * BPL1 + swz(b_row + h * 16, kk * 2 + b_chb);
                    LDSM4(bfr[h * 4 + 0], bfr[h * 4 + 1], bfr[h * 4 + 2], bfr[h * 4 + 3], bd);
                }
                const int nsa = (pb == 0) ? 2 : 1;
#pragma unroll
                for (int sa = 0; sa < nsa; ++sa)
#pragma unroll
                    for (int ma = 0; ma < 2; ++ma)
#pragma unroll
                        for (int na = 0; na < 8; ++na)
                            MMA16816(acc[ma][na], afr[sa][ma], &bfr[na * 2]);
            }
        }
    };

    // ---- prologue ----
    ldg_A(0); sts_A_split(0);
    load_B(0, 0); CP_COMMIT();
    load_B(1, 1); CP_COMMIT();
    ldg_A(1);

    // ---- main loop: ONE sync per stage ----
    int buf = 0;
    for (int ks = 0; ks < NST1; ++ks) {
        int b1 = (buf + 1 == 3) ? 0 : buf + 1;
        int b2 = (b1 + 1 == 3) ? 0 : b1 + 1;
        if (ks + 1 < NST1) sts_A_split(b1);
        if (ks + 2 < NST1) ldg_A(ks + 2);
        if (ks + 1 < NST1) { CP_WAIT1(); } else { CP_WAIT0(); }
        __syncthreads();
        if (ks + 2 < NST1) { load_B(ks + 2, b2); CP_COMMIT(); }
        compute(buf);
        buf = b1;
    }

    // ---- epilogue ----
#pragma unroll
    for (int ma = 0; ma < 2; ++ma) {
        int row0 = m0 + mbase + ma * 16 + (lane >> 2);
#pragma unroll
        for (int na = 0; na < 8; ++na) {
            int col0 = nbase + na * 8 + (lane & 3) * 2;
            const float* a4 = acc[ma][na];
#pragma unroll
            for (int h = 0; h < 2; ++h) {
                int row = row0 + h * 8;
                float cx = __fmul_rn(a4[h * 2 + 0], INV_S1);
                float cy = __fmul_rn(a4[h * 2 + 1], INV_S1);
                float2 o = make_float2(__fadd_rn(cx, bias[col0]),
                                       __fadd_rn(cy, bias[col0 + 1]));
                *(float2*)(Hout + (size_t)row * H_ + col0) = o;
            }
        }
    }
}

// ======================= L2/L3 GEMM: 128Mx128N, 256 thr, 3-stage ============
// MODE 2: epi LIF -> fp16 spikes ; MODE 3: N=100 predicated, epi LIF -> fp32
#define NST2 (H_ / 32)            // 8
#define APL2 8192
#define BPL2 8192
#define STG2 (APL2 + 2 * BPL2)    // 24576
#define SMEM2 (3 * STG2)          // 73728

template <int MODE>
__global__ void __launch_bounds__(256, 2) mma_gemm23(
    const __half* __restrict__ Ahf, const __half* __restrict__ Ws,
    const float* __restrict__ bias, __half* __restrict__ Sb,
    float* __restrict__ Sf, float* __restrict__ V, int t) {
    constexpr size_t PL = (MODE == 2) ? (size_t)H_ * H_ : (size_t)128 * H_;
    extern __shared__ char smem[];
    const uint32_t sb = smem_u32(smem);
    const int tid = threadIdx.x;
    const int lane = tid & 31;
    const int wid = tid >> 5;
    const int m0 = blockIdx.x * 128;
    const int n0 = blockIdx.y * 128;
    const int mbase = (wid >> 2) * 64;
    const int nbase = (wid & 3) * 32;

    float acc[4][4][4];
#pragma unroll
    for (int i = 0; i < 4; ++i)
#pragma unroll
        for (int j = 0; j < 4; ++j)
#pragma unroll
            for (int k = 0; k < 4; ++k) acc[i][j][k] = 0.0f;

    auto load_stage = [&](int ks, int buf) {
        int kc = ks * 32;
        uint32_t ab = sb + buf * STG2;
#pragma unroll
        for (int u = 0; u < 2; ++u) {
            int f = tid + u * 256;
            int r = f >> 2, c = f & 3;
            CP_ASYNC16(ab + swz(r, c), Ahf + (size_t)(m0 + r) * H_ + kc + c * 8);
        }
        uint32_t bb = ab + APL2;
#pragma unroll
        for (int u = 0; u < 4; ++u) {
            int f = tid + u * 256;
            int s = f >> 9, rem = f & 511, r = rem >> 2, c = rem & 3;
            const __half* src = Ws + (size_t)s * PL + (size_t)(n0 + r) * H_ + kc + c * 8;
            CP_ASYNC16(bb + s * BPL2 + swz(r, c), src);
        }
    };

    const int a_row = mbase + (lane & 7) + ((lane >> 3) & 1) * 8;
    const int a_chb = (lane >> 4);
    const int b_row = nbase + (lane & 7) + (lane >> 4) * 8;
    const int b_chb = ((lane >> 3) & 1);

    auto compute = [&](int buf) {
        uint32_t ab = sb + buf * STG2;
        uint32_t bb = ab + APL2;
#pragma unroll
        for (int kk = 0; kk < 2; ++kk) {
            uint32_t afr[4][4];
#pragma unroll
            for (int ma = 0; ma < 4; ++ma) {
                uint32_t ad = ab + swz(a_row + ma * 16, kk * 2 + a_chb);
                LDSM4(afr[ma][0], afr[ma][1], afr[ma][2], afr[ma][3], ad);
            }
#pragma unroll
            for (int pb = 0; pb < 2; ++pb) {
                uint32_t bfr[8];
#pragma unroll
                for (int h = 0; h < 2; ++h) {
                    uint32_t bd = bb + pb * BPL2 + swz(b_row + h * 16, kk * 2 + b_chb);
                    LDSM4(bfr[h * 4 + 0], bfr[h * 4 + 1], bfr[h * 4 + 2], bfr[h * 4 + 3], bd);
                }
#pragma unroll
                for (int ma = 0; ma < 4; ++ma)
#pragma unroll
                    for (int na = 0; na < 4; ++na)
                        MMA16816(acc[ma][na], afr[ma], &bfr[na * 2]);
            }
        }
    };

    // ---- prologue ----
    load_stage(0, 0); CP_COMMIT();
    load_stage(1, 1); CP_COMMIT();

    // ---- main loop: ONE sync per stage ----
    int buf = 0;
    for (int ks = 0; ks < NST2; ++ks) {
        int b1 = (buf + 1 == 3) ? 0 : buf + 1;
        int b2 = (b1 + 1 == 3) ? 0 : b1 + 1;
        if (ks + 1 < NST2) { CP_WAIT1(); } else { CP_WAIT0(); }
        __syncthreads();
        if (ks + 2 < NST2) { load_stage(ks + 2, b2); CP_COMMIT(); }
        compute(buf);
        buf = b1;
    }

    // ---- epilogue ----
#pragma unroll
    for (int ma = 0; ma < 4; ++ma) {
        int row0 = m0 + mbase + ma * 16 + (lane >> 2);
#pragma unroll
        for (int na = 0; na < 4; ++na) {
            int col0 = n0 + nbase + na * 8 + (lane & 3) * 2;
            const float* a4 = acc[ma][na];
#pragma unroll
            for (int h = 0; h < 2; ++h) {
                int row = row0 + h * 8;
                float cx = __fmul_rn(a4[h * 2 + 0], INV_S2);
                float cy = __fmul_rn(a4[h * 2 + 1], INV_S2);
                if (MODE == 2) {
                    size_t idx = (size_t)row * H_ + col0;
                    float2 v = (t == 0) ? make_float2(0.f, 0.f) : *(float2*)(V + idx);
                    float hx = __fadd_rn(cx, bias[col0]);
                    float hy = __fadd_rn(cy, bias[col0 + 1]);
                    float vox, voy, sox, soy;
                    lif_c(hx, v.x, vox, sox);
                    lif_c(hy, v.y, voy, soy);
                    *(float2*)(V + idx) = make_float2(vox, voy);
                    *(uint32_t*)(Sb + idx) =
                        pack_h2(__float2half_rn(sox), __float2half_rn(soy));
                } else {
                    if (col0 < O_) {
                        size_t vidx = (size_t)row * 128 + col0;
                        float2 v = (t == 0) ? make_float2(0.f, 0.f) : *(float2*)(V + vidx);
                        float hx = __fadd_rn(cx, bias[col0]);
                        float hy = __fadd_rn(cy, bias[col0 + 1]);
                        float vox, voy, sox, soy;
                        lif_c(hx, v.x, vox, sox);
                        lif_c(hy, v.y, voy, soy);
                        *(float2*)(V + vidx) = make_float2(vox, voy);
                        *(float2*)(Sf + (size_t)row * O_ + col0) = make_float2(sox, soy);
                    }
                }
            }
        }
    }
}

// ======================= LIF layer 1 =======================
__global__ void lif1_kernel(const float* __restrict__ h1, float* __restrict__ v1,
                            __half* __restrict__ s1, int t) {
    int i = blockIdx.x * blockDim.x + threadIdx.x;
    int e = i * 4;
    int b = e >> 8;
    int h = e & 255;
    float4 hv = *(const float4*)(h1 + (size_t)(b * 3 + t) * H_ + h);
    float4 v = (t == 0) ? make_float4(0.f, 0.f, 0.f, 0.f) : *(const float4*)(v1 + e);
    float4 vo, so;
    lif_c(hv.x, v.x, vo.x, so.x);
    lif_c(hv.y, v.y, vo.y, so.y);
    lif_c(hv.z, v.z, vo.z, so.z);
    lif_c(hv.w, v.w, vo.w, so.w);
    *(float4*)(v1 + e) = vo;
    uint2 sp;
    sp.x = pack_h2(__float2half_rn(so.x), __float2half_rn(so.y));
    sp.y = pack_h2(__float2half_rn(so.z), __float2half_rn(so.w));
    *(uint2*)(s1 + e) = sp;
}

extern "C" void kernel_launch(void* const* d_in, const int* in_sizes, int n_in,
                              void* d_out, int out_size) {
    const float* dvs = (const float*)d_in[0];
    const float* W1  = (const float*)d_in[1];
    const float* b1  = (const float*)d_in[2];
    const float* W2  = (const float*)d_in[3];
    const float* b2  = (const float*)d_in[4];
    const float* W3  = (const float*)d_in[5];
    const float* b3  = (const float*)d_in[6];
    float* out = (float*)d_out;

    float *h1, *v1, *v2, *v3;
    __half *s1b, *s2b, *w1s, *w2s, *w3s;
    cudaGetSymbolAddress((void**)&h1, g_h1);
    cudaGetSymbolAddress((void**)&v1, g_v1);
    cudaGetSymbolAddress((void**)&v2, g_v2);
    cudaGetSymbolAddress((void**)&v3, g_v3);
    cudaGetSymbolAddress((void**)&s1b, g_s1b);
    cudaGetSymbolAddress((void**)&s2b, g_s2b);
    cudaGetSymbolAddress((void**)&w1s, g_W1s);
    cudaGetSymbolAddress((void**)&w2s, g_W2s);
    cudaGetSymbolAddress((void**)&w3s, g_W3s);

    cudaFuncSetAttribute(mma_gemm1, cudaFuncAttributeMaxDynamicSharedMemorySize, SMEM1);
    cudaFuncSetAttribute(mma_gemm23<2>, cudaFuncAttributeMaxDynamicSharedMemorySize, SMEM2);
    cudaFuncSetAttribute(mma_gemm23<3>, cudaFuncAttributeMaxDynamicSharedMemorySize, SMEM2);

    // weight splits (exact 2-way fp16, scale 2^6)
    split_w_kernel<<<(H_ * D_) / 256, 256>>>(W1, w1s, H_ * D_);
    split_w_kernel<<<(H_ * H_) / 256, 256>>>(W2, w2s, H_ * H_);
    split_w3_kernel<<<(128 * H_) / 256, 256>>>(W3);

    // layer 1, all timesteps: [B*T, D] @ W1^T -> g_h1  (128M x 256N tiles)
    mma_gemm1<<<(B_ * T_) / 128, 512, SMEM1>>>(dvs, w1s, b1, h1);

    for (int t = 0; t < T_; ++t) {
        lif1_kernel<<<(B_ * H_ / 4) / 256, 256>>>(h1, v1, s1b, t);
        mma_gemm23<2><<<dim3(B_ / 128, H_ / 128), 256, SMEM2>>>(
            s1b, w2s, b2, s2b, nullptr, v2, t);
        mma_gemm23<3><<<dim3(B_ / 128, 1), 256, SMEM2>>>(
            s2b, w3s, b3, nullptr, out, v3, t);
    }
}

// round 11
// speedup vs baseline: 3.0165x; 1.0264x over previous
#include <cuda_runtime.h>
#include <cuda_fp16.h>
#include <cstdint>

// ---------------------------------------------------------------------------
// NeuroVPR SNN via mma.sync fp16 2-way exact-split (scale 2^6).
//  L1: 128Mx256N CTA tiles, 512 thr, 3-buf single-sync pipeline,
//      fragment-level software pipelining (LDSM hidden under MMA).
//  L2/L3: spikes exact in fp16; W split 2-way -> 2 products; 3-stage pipe.
// ---------------------------------------------------------------------------

#define B_ 16384
#define T_ 3
#define D_ 2752
#define H_ 256
#define O_ 100

// ---- scratch ----
__device__ float g_h1[(size_t)B_ * T_ * H_];
__device__ float g_v1[(size_t)B_ * H_];
__device__ float g_v2[(size_t)B_ * H_];
__device__ float g_v3[(size_t)B_ * 128];
__device__ __half g_s1b[(size_t)B_ * H_];
__device__ __half g_s2b[(size_t)B_ * H_];
__device__ __half g_W1s[2 * H_ * D_];
__device__ __half g_W2s[2 * H_ * H_];
__device__ __half g_W3s[2 * 128 * H_];   // padded to 128 rows

#define WSCALE 64.0f
#define INV_S1 (1.0f / 4096.0f)   // L1: A and W both scaled 2^6
#define INV_S2 (1.0f / 64.0f)     // L2/3: only W scaled

// ======================= helpers =======================
__device__ __forceinline__ uint32_t smem_u32(const void* p) {
    uint32_t a;
    asm("{ .reg .u64 t; cvta.to.shared.u64 t, %1; cvt.u32.u64 %0, t; }"
        : "=r"(a) : "l"(p));
    return a;
}
#define CP_ASYNC16(dst, src) \
    asm volatile("cp.async.cg.shared.global [%0], [%1], 16;" :: "r"(dst), "l"(src))
#define CP_COMMIT() asm volatile("cp.async.commit_group;" ::: "memory")
#define CP_WAIT0() asm volatile("cp.async.wait_group 0;" ::: "memory")
#define CP_WAIT1() asm volatile("cp.async.wait_group 1;" ::: "memory")
#define LDSM4(r0, r1, r2, r3, addr) \
    asm volatile("ldmatrix.sync.aligned.m8n8.x4.shared.b16 {%0,%1,%2,%3}, [%4];" \
        : "=r"(r0), "=r"(r1), "=r"(r2), "=r"(r3) : "r"(addr))
#define MMA16816(d, a, b) \
    asm volatile("mma.sync.aligned.m16n8k16.row.col.f32.f16.f16.f32 " \
        "{%0,%1,%2,%3}, {%4,%5,%6,%7}, {%8,%9}, {%0,%1,%2,%3};" \
        : "+f"((d)[0]), "+f"((d)[1]), "+f"((d)[2]), "+f"((d)[3]) \
        : "r"((a)[0]), "r"((a)[1]), "r"((a)[2]), "r"((a)[3]), "r"((b)[0]), "r"((b)[1]))

__device__ __forceinline__ void split2(float x, __half& h, __half& l) {
    float xs = x * WSCALE;
    h = __float2half_rn(xs);
    l = __float2half_rn(xs - __half2float(h));
}
__device__ __forceinline__ uint32_t pack_h2(__half lo, __half hi) {
    return (uint32_t)__half_as_ushort(lo) | ((uint32_t)__half_as_ushort(hi) << 16);
}
__device__ __forceinline__ void lif_c(float hval, float vin, float& vout, float& sout) {
    float vn = __fadd_rn(vin, __fmul_rn(__fsub_rn(hval, vin), 0.5f));
    bool sp = (vn >= 1.0f);
    vout = sp ? 0.0f : vn;
    sout = sp ? 1.0f : 0.0f;
}
// swizzled byte offset inside an Rx32-f16 plane (row 64B = 4 x 16B chunks)
__device__ __forceinline__ uint32_t swz(int r, int c) {
    return (uint32_t)(r * 64 + ((c ^ ((r >> 1) & 3)) << 4));
}

// ======================= weight split kernels =======================
__global__ void split_w_kernel(const float* __restrict__ W, __half* dst, int n) {
    int i = blockIdx.x * 256 + threadIdx.x;
    __half h, l;
    split2(W[i], h, l);
    dst[i] = h; dst[i + n] = l;
}
__global__ void split_w3_kernel(const float* __restrict__ W3) {
    int i = blockIdx.x * 256 + threadIdx.x;      // over 128*H_
    int r = i >> 8, c = i & 255;
    float w = (r < O_) ? W3[r * H_ + c] : 0.0f;
    __half h, l;
    split2(w, h, l);
    g_W3s[i] = h; g_W3s[i + 128 * H_] = l;
}

// ======================= Layer-1 GEMM: 128Mx256N, 512 thr ===================
#define NST1 (D_ / 32)            // 86
#define APL1 8192                 // 128 rows x 64 B
#define AB1  (2 * APL1)           // 16384
#define BPL1 16384                // 256 rows x 64 B
#define STG1 (AB1 + 2 * BPL1)     // 49152
#define SMEM1 (3 * STG1)          // 147456

__global__ void __launch_bounds__(512, 1) mma_gemm1(
    const float* __restrict__ Af32, const __half* __restrict__ Ws,
    const float* __restrict__ bias, float* __restrict__ Hout) {
    extern __shared__ char smem[];
    const uint32_t sb = smem_u32(smem);
    const int tid = threadIdx.x;
    const int lane = tid & 31;
    const int wid = tid >> 5;
    const int m0 = blockIdx.x * 128;
    const int mbase = (wid & 3) * 32;
    const int nbase = (wid >> 2) * 64;

    float acc[2][8][4];
#pragma unroll
    for (int i = 0; i < 2; ++i)
#pragma unroll
        for (int j = 0; j < 8; ++j)
#pragma unroll
            for (int k = 0; k < 4; ++k) acc[i][j][k] = 0.0f;

    float4 ra2[2];
    const int lr = tid >> 2, lc = tid & 3;

    auto ldg_A = [&](int ks) {
        const float* g = Af32 + (size_t)(m0 + lr) * D_ + ks * 32 + lc * 8;
        ra2[0] = *(const float4*)g;
        ra2[1] = *(const float4*)(g + 4);
    };
    auto sts_A_split = [&](int buf) {
        uint32_t ab = sb + buf * STG1;
        float x[8] = {ra2[0].x, ra2[0].y, ra2[0].z, ra2[0].w,
                      ra2[1].x, ra2[1].y, ra2[1].z, ra2[1].w};
        __half s0[8], s1[8];
#pragma unroll
        for (int j = 0; j < 8; ++j) split2(x[j], s0[j], s1[j]);
        uint32_t off = swz(lr, lc);
        uint4 v0 = make_uint4(pack_h2(s0[0], s0[1]), pack_h2(s0[2], s0[3]),
                              pack_h2(s0[4], s0[5]), pack_h2(s0[6], s0[7]));
        uint4 v1 = make_uint4(pack_h2(s1[0], s1[1]), pack_h2(s1[2], s1[3]),
                              pack_h2(s1[4], s1[5]), pack_h2(s1[6], s1[7]));
        asm volatile("st.shared.v4.b32 [%0], {%1,%2,%3,%4};" :: "r"(ab + off),
                     "r"(v0.x), "r"(v0.y), "r"(v0.z), "r"(v0.w));
        asm volatile("st.shared.v4.b32 [%0], {%1,%2,%3,%4};" :: "r"(ab + APL1 + off),
                     "r"(v1.x), "r"(v1.y), "r"(v1.z), "r"(v1.w));
    };
    auto load_B = [&](int ks, int buf) {
        int kc = ks * 32;
        uint32_t bb = sb + buf * STG1 + AB1;
#pragma unroll
        for (int u = 0; u < 4; ++u) {
            int f = tid + u * 512;
            int s = f >> 10, rem = f & 1023, r = rem >> 2, c = rem & 3;
            const __half* src = Ws + (size_t)s * (H_ * D_) + (size_t)r * D_ + kc + c * 8;
            CP_ASYNC16(bb + s * BPL1 + swz(r, c), src);
        }
    };

    const int a_row = mbase + (lane & 7) + ((lane >> 3) & 1) * 8;
    const int a_chb = (lane >> 4);
    const int b_row = nbase + (lane & 7) + (lane >> 4) * 8;
    const int b_chb = ((lane >> 3) & 1);

    // fragment loaders
    auto ldsmA = [&](uint32_t ab, int plane, int kk, uint32_t* dst) {  // 8 regs
#pragma unroll
        for (int ma = 0; ma < 2; ++ma) {
            uint32_t ad = ab + plane * APL1 + swz(a_row + ma * 16, kk * 2 + a_chb);
            LDSM4(dst[ma * 4 + 0], dst[ma * 4 + 1], dst[ma * 4 + 2], dst[ma * 4 + 3], ad);
        }
    };
    auto ldsmB = [&](uint32_t bb, int pb, int kk, uint32_t* dst) {     // 16 regs
#pragma unroll
        for (int h = 0; h < 4; ++h) {
            uint32_t bd = bb + pb * BPL1 + swz(b_row + h * 16, kk * 2 + b_chb);
            LDSM4(dst[h * 4 + 0], dst[h * 4 + 1], dst[h * 4 + 2], dst[h * 4 + 3], bd);
        }
    };
    auto mmaP = [&](const uint32_t* a, const uint32_t* b) {            // 16 MMAs
#pragma unroll
        for (int ma = 0; ma < 2; ++ma)
#pragma unroll
            for (int na = 0; na < 8; ++na)
                MMA16816(acc[ma][na], &a[ma * 4], &b[na * 2]);
    };

    // software-pipelined stage: only the first 8 LDSM are exposed after the
    // barrier; every other LDSM group issues between independent MMA groups.
    auto compute = [&](int buf) {
        uint32_t ab = sb + buf * STG1;
        uint32_t bb = ab + AB1;
        uint32_t a0[8], a1[8], a0n[8], bx[16], by[16];
        ldsmA(ab, 0, 0, a0);
        ldsmA(ab, 1, 0, a1);
        ldsmB(bb, 0, 0, bx);
        // ---- kk = 0 ----
        ldsmB(bb, 1, 0, by);          // B1(kk0) hidden under next 32 MMAs
        mmaP(a0, bx);
        mmaP(a1, bx);
        ldsmA(ab, 0, 1, a0n);         // A(kk1) hidden under B1 MMAs
        ldsmA(ab, 1, 1, a1);          // plane1 reload (kk0 uses done)
        ldsmB(bb, 0, 1, bx);          // B0(kk1)
        mmaP(a0, by);
        // ---- kk = 1 ----
        ldsmB(bb, 1, 1, by);
        mmaP(a0n, bx);
        mmaP(a1, bx);
        mmaP(a0n, by);
    };

    // ---- prologue ----
    ldg_A(0); sts_A_split(0);
    load_B(0, 0); CP_COMMIT();
    load_B(1, 1); CP_COMMIT();
    ldg_A(1);

    // ---- main loop: ONE sync per stage ----
    int buf = 0;
    for (int ks = 0; ks < NST1; ++ks) {
        int b1 = (buf + 1 == 3) ? 0 : buf + 1;
        int b2 = (b1 + 1 == 3) ? 0 : b1 + 1;
        if (ks + 1 < NST1) sts_A_split(b1);
        if (ks + 2 < NST1) ldg_A(ks + 2);
        if (ks + 1 < NST1) { CP_WAIT1(); } else { CP_WAIT0(); }
        __syncthreads();
        if (ks + 2 < NST1) { load_B(ks + 2, b2); CP_COMMIT(); }
        compute(buf);
        buf = b1;
    }

    // ---- epilogue ----
#pragma unroll
    for (int ma = 0; ma < 2; ++ma) {
        int row0 = m0 + mbase + ma * 16 + (lane >> 2);
#pragma unroll
        for (int na = 0; na < 8; ++na) {
            int col0 = nbase + na * 8 + (lane & 3) * 2;
            const float* a4 = acc[ma][na];
#pragma unroll
            for (int h = 0; h < 2; ++h) {
                int row = row0 + h * 8;
                float cx = __fmul_rn(a4[h * 2 + 0], INV_S1);
                float cy = __fmul_rn(a4[h * 2 + 1], INV_S1);
                float2 o = make_float2(__fadd_rn(cx, bias[col0]),
                                       __fadd_rn(cy, bias[col0 + 1]));
                *(float2*)(Hout + (size_t)row * H_ + col0) = o;
            }
        }
    }
}

// ======================= L2/L3 GEMM: 128Mx128N, 256 thr, 3-stage ============
#define NST2 (H_ / 32)            // 8
#define APL2 8192
#define BPL2 8192
#define STG2 (APL2 + 2 * BPL2)    // 24576
#define SMEM2 (3 * STG2)          // 73728

template <int MODE>
__global__ void __launch_bounds__(256, 2) mma_gemm23(
    const __half* __restrict__ Ahf, const __half* __restrict__ Ws,
    const float* __restrict__ bias, __half* __restrict__ Sb,
    float* __restrict__ Sf, float* __restrict__ V, int t) {
    constexpr size_t PL = (MODE == 2) ? (size_t)H_ * H_ : (size_t)128 * H_;
    extern __shared__ char smem[];
    const uint32_t sb = smem_u32(smem);
    const int tid = threadIdx.x;
    const int lane = tid & 31;
    const int wid = tid >> 5;
    const int m0 = blockIdx.x * 128;
    const int n0 = blockIdx.y * 128;
    const int mbase = (wid >> 2) * 64;
    const int nbase = (wid & 3) * 32;

    float acc[4][4][4];
#pragma unroll
    for (int i = 0; i < 4; ++i)
#pragma unroll
        for (int j = 0; j < 4; ++j)
#pragma unroll
            for (int k = 0; k < 4; ++k) acc[i][j][k] = 0.0f;

    auto load_stage = [&](int ks, int buf) {
        int kc = ks * 32;
        uint32_t ab = sb + buf * STG2;
#pragma unroll
        for (int u = 0; u < 2; ++u) {
            int f = tid + u * 256;
            int r = f >> 2, c = f & 3;
            CP_ASYNC16(ab + swz(r, c), Ahf + (size_t)(m0 + r) * H_ + kc + c * 8);
        }
        uint32_t bb = ab + APL2;
#pragma unroll
        for (int u = 0; u < 4; ++u) {
            int f = tid + u * 256;
            int s = f >> 9, rem = f & 511, r = rem >> 2, c = rem & 3;
            const __half* src = Ws + (size_t)s * PL + (size_t)(n0 + r) * H_ + kc + c * 8;
            CP_ASYNC16(bb + s * BPL2 + swz(r, c), src);
        }
    };

    const int a_row = mbase + (lane & 7) + ((lane >> 3) & 1) * 8;
    const int a_chb = (lane >> 4);
    const int b_row = nbase + (lane & 7) + (lane >> 4) * 8;
    const int b_chb = ((lane >> 3) & 1);

    auto compute = [&](int buf) {
        uint32_t ab = sb + buf * STG2;
        uint32_t bb = ab + APL2;
#pragma unroll
        for (int kk = 0; kk < 2; ++kk) {
            uint32_t afr[4][4];
#pragma unroll
            for (int ma = 0; ma < 4; ++ma) {
                uint32_t ad = ab + swz(a_row + ma * 16, kk * 2 + a_chb);
                LDSM4(afr[ma][0], afr[ma][1], afr[ma][2], afr[ma][3], ad);
            }
#pragma unroll
            for (int pb = 0; pb < 2; ++pb) {
                uint32_t bfr[8];
#pragma unroll
                for (int h = 0; h < 2; ++h) {
                    uint32_t bd = bb + pb * BPL2 + swz(b_row + h * 16, kk * 2 + b_chb);
                    LDSM4(bfr[h * 4 + 0], bfr[h * 4 + 1], bfr[h * 4 + 2], bfr[h * 4 + 3], bd);
                }
#pragma unroll
                for (int ma = 0; ma < 4; ++ma)
#pragma unroll
                    for (int na = 0; na < 4; ++na)
                        MMA16816(acc[ma][na], afr[ma], &bfr[na * 2]);
            }
        }
    };

    load_stage(0, 0); CP_COMMIT();
    load_stage(1, 1); CP_COMMIT();

    int buf = 0;
    for (int ks = 0; ks < NST2; ++ks) {
        int b1 = (buf + 1 == 3) ? 0 : buf + 1;
        int b2 = (b1 + 1 == 3) ? 0 : b1 + 1;
        if (ks + 1 < NST2) { CP_WAIT1(); } else { CP_WAIT0(); }
        __syncthreads();
        if (ks + 2 < NST2) { load_stage(ks + 2, b2); CP_COMMIT(); }
        compute(buf);
        buf = b1;
    }

#pragma unroll
    for (int ma = 0; ma < 4; ++ma) {
        int row0 = m0 + mbase + ma * 16 + (lane >> 2);
#pragma unroll
        for (int na = 0; na < 4; ++na) {
            int col0 = n0 + nbase + na * 8 + (lane & 3) * 2;
            const float* a4 = acc[ma][na];
#pragma unroll
            for (int h = 0; h < 2; ++h) {
                int row = row0 + h * 8;
                float cx = __fmul_rn(a4[h * 2 + 0], INV_S2);
                float cy = __fmul_rn(a4[h * 2 + 1], INV_S2);
                if (MODE == 2) {
                    size_t idx = (size_t)row * H_ + col0;
                    float2 v = (t == 0) ? make_float2(0.f, 0.f) : *(float2*)(V + idx);
                    float hx = __fadd_rn(cx, bias[col0]);
                    float hy = __fadd_rn(cy, bias[col0 + 1]);
                    float vox, voy, sox, soy;
                    lif_c(hx, v.x, vox, sox);
                    lif_c(hy, v.y, voy, soy);
                    *(float2*)(V + idx) = make_float2(vox, voy);
                    *(uint32_t*)(Sb + idx) =
                        pack_h2(__float2half_rn(sox), __float2half_rn(soy));
                } else {
                    if (col0 < O_) {
                        size_t vidx = (size_t)row * 128 + col0;
                        float2 v = (t == 0) ? make_float2(0.f, 0.f) : *(float2*)(V + vidx);
                        float hx = __fadd_rn(cx, bias[col0]);
                        float hy = __fadd_rn(cy, bias[col0 + 1]);
                        float vox, voy, sox, soy;
                        lif_c(hx, v.x, vox, sox);
                        lif_c(hy, v.y, voy, soy);
                        *(float2*)(V + vidx) = make_float2(vox, voy);
                        *(float2*)(Sf + (size_t)row * O_ + col0) = make_float2(sox, soy);
                    }
                }
            }
        }
    }
}

// ======================= LIF layer 1 =======================
__global__ void lif1_kernel(const float* __restrict__ h1, float* __restrict__ v1,
                            __half* __restrict__ s1, int t) {
    int i = blockIdx.x * blockDim.x + threadIdx.x;
    int e = i * 4;
    int b = e >> 8;
    int h = e & 255;
    float4 hv = *(const float4*)(h1 + (size_t)(b * 3 + t) * H_ + h);
    float4 v = (t == 0) ? make_float4(0.f, 0.f, 0.f, 0.f) : *(const float4*)(v1 + e);
    float4 vo, so;
    lif_c(hv.x, v.x, vo.x, so.x);
    lif_c(hv.y, v.y, vo.y, so.y);
    lif_c(hv.z, v.z, vo.z, so.z);
    lif_c(hv.w, v.w, vo.w, so.w);
    *(float4*)(v1 + e) = vo;
    uint2 sp;
    sp.x = pack_h2(__float2half_rn(so.x), __float2half_rn(so.y));
    sp.y = pack_h2(__float2half_rn(so.z), __float2half_rn(so.w));
    *(uint2*)(s1 + e) = sp;
}

extern "C" void kernel_launch(void* const* d_in, const int* in_sizes, int n_in,
                              void* d_out, int out_size) {
    const float* dvs = (const float*)d_in[0];
    const float* W1  = (const float*)d_in[1];
    const float* b1  = (const float*)d_in[2];
    const float* W2  = (const float*)d_in[3];
    const float* b2  = (const float*)d_in[4];
    const float* W3  = (const float*)d_in[5];
    const float* b3  = (const float*)d_in[6];
    float* out = (float*)d_out;

    float *h1, *v1, *v2, *v3;
    __half *s1b, *s2b, *w1s, *w2s, *w3s;
    cudaGetSymbolAddress((void**)&h1, g_h1);
    cudaGetSymbolAddress((void**)&v1, g_v1);
    cudaGetSymbolAddress((void**)&v2, g_v2);
    cudaGetSymbolAddress((void**)&v3, g_v3);
    cudaGetSymbolAddress((void**)&s1b, g_s1b);
    cudaGetSymbolAddress((void**)&s2b, g_s2b);
    cudaGetSymbolAddress((void**)&w1s, g_W1s);
    cudaGetSymbolAddress((void**)&w2s, g_W2s);
    cudaGetSymbolAddress((void**)&w3s, g_W3s);

    cudaFuncSetAttribute(mma_gemm1, cudaFuncAttributeMaxDynamicSharedMemorySize, SMEM1);
    cudaFuncSetAttribute(mma_gemm23<2>, cudaFuncAttributeMaxDynamicSharedMemorySize, SMEM2);
    cudaFuncSetAttribute(mma_gemm23<3>, cudaFuncAttributeMaxDynamicSharedMemorySize, SMEM2);

    // weight splits (exact 2-way fp16, scale 2^6)
    split_w_kernel<<<(H_ * D_) / 256, 256>>>(W1, w1s, H_ * D_);
    split_w_kernel<<<(H_ * H_) / 256, 256>>>(W2, w2s, H_ * H_);
    split_w3_kernel<<<(128 * H_) / 256, 256>>>(W3);

    // layer 1, all timesteps: [B*T, D] @ W1^T -> g_h1  (128M x 256N tiles)
    mma_gemm1<<<(B_ * T_) / 128, 512, SMEM1>>>(dvs, w1s, b1, h1);

    for (int t = 0; t < T_; ++t) {
        lif1_kernel<<<(B_ * H_ / 4) / 256, 256>>>(h1, v1, s1b, t);
        mma_gemm23<2><<<dim3(B_ / 128, H_ / 128), 256, SMEM2>>>(
            s1b, w2s, b2, s2b, nullptr, v2, t);
        mma_gemm23<3><<<dim3(B_ / 128, 1), 256, SMEM2>>>(
            s2b, w3s, b3, nullptr, out, v3, t);
    }
}